// round 2
// baseline (speedup 1.0000x reference)
#include <cuda_runtime.h>
#include <cstddef>

#define BATCH 256
#define SEQ   512
#define DIN   64
#define HID   512
#define NGRP  8
#define GCTA  16
#define GRIDN (NGRP*GCTA)
#define NTH   256
#define BR    32          // batch rows per group
#define NS    32          // hidden slice per CTA
#define KA    576
#define KB    1024
#define KAQ   (KA/4)      // 144 per k-group
#define KBQ   (KB/4)      // 256 per k-group
#define CH    16          // k-chunk
#define NCA   (KAQ/CH)    // 9
#define NCB   (KBQ/CH)    // 16
#define PST   36          // padded partial-row stride (floats)

#define WA_FL (KA*NS)         // 18432 floats
#define WB_FL (KB*NS)         // 32768 floats
#define S_FL  (4*BR*PST)      // 4608 floats (>= 4*2*CH*BR = 4096 staging)
#define SMEM_BYTES ((WA_FL + WB_FL + S_FL) * 4)   // 223,232 B

// cross-CTA state (static device scratch; allocation-free)
__device__ float g_H1[2][BATCH * HID];
__device__ float g_H2[2][BATCH * HID];
__device__ unsigned g_cnt[NGRP];
__device__ unsigned g_gen[NGRP];

// ---------------- f32x2 packed helpers (FFMA2 path, sm_100+) ----------------
__device__ __forceinline__ unsigned long long dupf(float a) {
    unsigned long long d;
    asm("mov.b64 %0, {%1, %1};" : "=l"(d) : "f"(a));
    return d;
}
__device__ __forceinline__ void fma2(unsigned long long& d,
                                     unsigned long long a, unsigned long long b) {
    asm("fma.rn.f32x2 %0, %1, %2, %0;" : "+l"(d) : "l"(a), "l"(b));
}
__device__ __forceinline__ float2 unpk(unsigned long long v) {
    float2 r;
    asm("mov.b64 {%0, %1}, %2;" : "=f"(r.x), "=f"(r.y) : "l"(v));
    return r;
}

// ---------------- 16-CTA group barrier ----------------
__device__ __forceinline__ void group_bar(int g, unsigned& target) {
    __threadfence();          // publish this thread's global stores
    __syncthreads();
    if (threadIdx.x == 0) {
        unsigned old = atomicAdd(&g_cnt[g], 1u);
        if (old == GCTA - 1u) {
            atomicExch(&g_cnt[g], 0u);
            __threadfence();
            atomicAdd(&g_gen[g], 1u);
        } else {
            while ((int)(*(volatile unsigned*)(g_gen + g) - target) < 0) {}
        }
        __threadfence();
    }
    __syncthreads();
    target++;
}

// ---------------- one GEMM slice: D[32m x 32n] partial for this k-group ----------------
// Writes fp32 partials into S (P layout [kq][m][PST]).
__device__ __forceinline__ void gemm_slice(
    const float* __restrict__ Wk,    // weights for this kq slice: [KQ][NS]
    float* __restrict__ S,
    const float* __restrict__ rowA,  // per-thread source row (k < split)
    const float* __restrict__ rowB,  // per-thread source row (k >= split), index k-split
    int split, int kbase, int NC,
    int kq, int ml, int half, int tm4, int tn4)
{
    unsigned long long acc[4][2];
#pragma unroll
    for (int i = 0; i < 4; i++) { acc[i][0] = 0ull; acc[i][1] = 0ull; }

    float* Asq = S + kq * (2 * CH * BR);

    auto ld2 = [&](int c, float4& fa, float4& fb) {
        int kg = kbase + c * CH + half * 8;
        const float* p = (kg < split) ? (rowA + kg) : (rowB + (kg - split));
        fa = __ldcg((const float4*)p);
        fb = __ldcg((const float4*)(p + 4));
    };
    auto st2 = [&](int buf, const float4& fa, const float4& fb) {
        float* d = Asq + buf * (CH * BR) + (half * 8) * BR + ml;
        d[0 * BR] = fa.x; d[1 * BR] = fa.y; d[2 * BR] = fa.z; d[3 * BR] = fa.w;
        d[4 * BR] = fb.x; d[5 * BR] = fb.y; d[6 * BR] = fb.z; d[7 * BR] = fb.w;
    };

    float4 fa, fb;
    ld2(0, fa, fb);
    st2(0, fa, fb);
    __syncthreads();

    for (int c = 0; c < NC; ++c) {
        float4 na, nb;
        bool more = (c + 1 < NC);
        if (more) ld2(c + 1, na, nb);

        const float* Ab = Asq + (c & 1) * (CH * BR);
        const float* Wc = Wk + c * CH * NS;
#pragma unroll
        for (int kk = 0; kk < CH; ++kk) {
            float4 av = *(const float4*)(Ab + kk * BR + tm4);
            ulonglong2 wv = *(const ulonglong2*)(Wc + kk * NS + tn4);
            unsigned long long a0 = dupf(av.x), a1 = dupf(av.y),
                               a2 = dupf(av.z), a3 = dupf(av.w);
            fma2(acc[0][0], a0, wv.x); fma2(acc[0][1], a0, wv.y);
            fma2(acc[1][0], a1, wv.x); fma2(acc[1][1], a1, wv.y);
            fma2(acc[2][0], a2, wv.x); fma2(acc[2][1], a2, wv.y);
            fma2(acc[3][0], a3, wv.x); fma2(acc[3][1], a3, wv.y);
        }
        if (more) st2((c + 1) & 1, na, nb);
        __syncthreads();
    }

    // write partials (As is dead after the final syncthreads above)
    float* P = S + kq * (BR * PST);
#pragma unroll
    for (int i = 0; i < 4; i++) {
        float2 lo = unpk(acc[i][0]);
        float2 hi = unpk(acc[i][1]);
        *(float4*)(P + (tm4 + i) * PST + tn4) = make_float4(lo.x, lo.y, hi.x, hi.y);
    }
}

__global__ void __launch_bounds__(NTH, 1) rnn_group(
    const float* __restrict__ x,
    const float* __restrict__ W_ih0, const float* __restrict__ W_hh0,
    const float* __restrict__ b_ih0, const float* __restrict__ b_hh0,
    const float* __restrict__ W_ih1, const float* __restrict__ W_hh1,
    const float* __restrict__ b_ih1, const float* __restrict__ b_hh1,
    const float* __restrict__ W_fc,  const float* __restrict__ b_fc,
    float* __restrict__ out)
{
    const int tid = threadIdx.x;
    const int bid = blockIdx.x;
    const int g   = bid >> 4;
    const int r   = bid & 15;
    const int n0  = r * NS;

    extern __shared__ float sm[];
    float* Wa = sm;                  // [KA][NS]
    float* Wb = Wa + WA_FL;          // [KB][NS]
    float* S  = Wb + WB_FL;          // staging / partials scratch
    __shared__ unsigned sBase;

    if (tid == 0) sBase = *(volatile unsigned*)(g_gen + g);

    // ---- one-time: weight slices -> SMEM (coalesced over k) ----
    for (int idx = tid; idx < WA_FL; idx += NTH) {
        int n = idx / KA, k = idx - n * KA;
        int ngl = n0 + n;
        Wa[k * NS + n] = (k < DIN) ? W_ih0[ngl * DIN + k]
                                   : W_hh0[ngl * HID + (k - DIN)];
    }
    for (int idx = tid; idx < WB_FL; idx += NTH) {
        int n = idx / KB, k = idx - n * KB;
        int ngl = n0 + n;
        Wb[k * NS + n] = (k < HID) ? W_ih1[ngl * HID + k]
                                   : W_hh1[ngl * HID + (k - HID)];
    }

    // ---- zero the t=-1 hidden buffers (buf 1) for this CTA's 2 batch rows ----
    {
        int b0 = g * BR + r * 2;
        float4 z = make_float4(0.f, 0.f, 0.f, 0.f);
        for (int i = tid; i < 256; i += NTH) {       // 2 rows * 512 / 4
            int row = b0 + (i >> 7);
            int col = (i & 127) * 4;
            *(float4*)(&g_H1[1][row * HID + col]) = z;
            *(float4*)(&g_H2[1][row * HID + col]) = z;
        }
    }
    __syncthreads();
    unsigned target = sBase + 1;
    group_bar(g, target);

    // ---- role indices ----
    const int ti   = tid & 63;       // lane within k-group
    const int kq   = tid >> 6;       // k-group 0..3
    const int tm4  = (ti & 7) * 4;   // m quad base
    const int tn4  = (ti >> 3) * 4;  // n quad base
    const int ml   = ti & 31;        // staging: local batch row
    const int half = ti >> 5;        // staging: k-half of chunk
    const int mg   = g * BR + ml;    // global batch row (staging)

    const float* xrow = x + (size_t)mg * SEQ * DIN;

    // reduce role: thread -> (rm, rn4)
    const int rm  = tid >> 3;
    const int rn4 = (tid & 7) * 4;
    const int mgr = g * BR + rm;
    float4 bA, bB;
    {
        float4 bi = *(const float4*)(b_ih0 + n0 + rn4);
        float4 bh = *(const float4*)(b_hh0 + n0 + rn4);
        bA = make_float4(bi.x + bh.x, bi.y + bh.y, bi.z + bh.z, bi.w + bh.w);
        bi = *(const float4*)(b_ih1 + n0 + rn4);
        bh = *(const float4*)(b_hh1 + n0 + rn4);
        bB = make_float4(bi.x + bh.x, bi.y + bh.y, bi.z + bh.z, bi.w + bh.w);
    }

    for (int t = 0; t < SEQ; ++t) {
        float*       h1c = g_H1[t & 1];
        const float* h1p = g_H1[(t & 1) ^ 1];
        float*       h2c = g_H2[t & 1];
        const float* h2p = g_H2[(t & 1) ^ 1];

        // ================= layer 0: h1_t = tanh(W_ih0 x_t + W_hh0 h1_{t-1} + b) =================
        gemm_slice(Wa + kq * KAQ * NS, S,
                   xrow + t * DIN,                 // k < 64 -> x
                   h1p + (size_t)mg * HID,         // k >= 64 -> h1 prev
                   DIN, kq * KAQ, NCA, kq, ml, half, tm4, tn4);
        __syncthreads();
        {
            const float* P = S + rm * PST + rn4;
            float4 p0 = *(const float4*)(P + 0 * BR * PST);
            float4 p1 = *(const float4*)(P + 1 * BR * PST);
            float4 p2 = *(const float4*)(P + 2 * BR * PST);
            float4 p3 = *(const float4*)(P + 3 * BR * PST);
            float4 hv;
            hv.x = tanhf(bA.x + p0.x + p1.x + p2.x + p3.x);
            hv.y = tanhf(bA.y + p0.y + p1.y + p2.y + p3.y);
            hv.z = tanhf(bA.z + p0.z + p1.z + p2.z + p3.z);
            hv.w = tanhf(bA.w + p0.w + p1.w + p2.w + p3.w);
            __stcg((float4*)(h1c + (size_t)mgr * HID + n0 + rn4), hv);
        }
        group_bar(g, target);

        // ================= layer 1: h2_t = tanh(W_ih1 h1_t + W_hh1 h2_{t-1} + b) =================
        gemm_slice(Wb + kq * KBQ * NS, S,
                   h1c + (size_t)mg * HID,         // k < 512 -> h1 current
                   h2p + (size_t)mg * HID,         // k >= 512 -> h2 prev
                   HID, kq * KBQ, NCB, kq, ml, half, tm4, tn4);
        __syncthreads();
        {
            const float* P = S + rm * PST + rn4;
            float4 p0 = *(const float4*)(P + 0 * BR * PST);
            float4 p1 = *(const float4*)(P + 1 * BR * PST);
            float4 p2 = *(const float4*)(P + 2 * BR * PST);
            float4 p3 = *(const float4*)(P + 3 * BR * PST);
            float4 hv;
            hv.x = tanhf(bB.x + p0.x + p1.x + p2.x + p3.x);
            hv.y = tanhf(bB.y + p0.y + p1.y + p2.y + p3.y);
            hv.z = tanhf(bB.z + p0.z + p1.z + p2.z + p3.z);
            hv.w = tanhf(bB.w + p0.w + p1.w + p2.w + p3.w);
            __stcg((float4*)(h2c + (size_t)mgr * HID + n0 + rn4), hv);
        }
        group_bar(g, target);
    }

    // ================= final FC: out[b] = h2[-1][b,:] . W_fc + b_fc =================
    const float* h2f = g_H2[(SEQ - 1) & 1];
    for (int r2 = 0; r2 < 2; ++r2) {
        int b = g * BR + r * 2 + r2;
        const float* hrow = h2f + (size_t)b * HID;
        float s = 0.f;
        for (int h = tid; h < HID; h += NTH)
            s += __ldcg(hrow + h) * W_fc[h];
#pragma unroll
        for (int off = 16; off; off >>= 1)
            s += __shfl_down_sync(0xffffffffu, s, off);
        if ((tid & 31) == 0) S[tid >> 5] = s;
        __syncthreads();
        if (tid == 0) {
            float tot = b_fc[0];
#pragma unroll
            for (int w = 0; w < 8; w++) tot += S[w];
            out[b] = tot;
        }
        __syncthreads();
    }
}

extern "C" void kernel_launch(void* const* d_in, const int* in_sizes, int n_in,
                              void* d_out, int out_size) {
    (void)in_sizes; (void)n_in; (void)out_size;
    const float* x     = (const float*)d_in[0];
    const float* W_ih0 = (const float*)d_in[1];
    const float* W_hh0 = (const float*)d_in[2];
    const float* b_ih0 = (const float*)d_in[3];
    const float* b_hh0 = (const float*)d_in[4];
    const float* W_ih1 = (const float*)d_in[5];
    const float* W_hh1 = (const float*)d_in[6];
    const float* b_ih1 = (const float*)d_in[7];
    const float* b_hh1 = (const float*)d_in[8];
    const float* W_fc  = (const float*)d_in[9];
    const float* b_fc  = (const float*)d_in[10];
    float* out = (float*)d_out;

    cudaFuncSetAttribute(rnn_group,
                         cudaFuncAttributeMaxDynamicSharedMemorySize, SMEM_BYTES);
    rnn_group<<<GRIDN, NTH, SMEM_BYTES>>>(
        x, W_ih0, W_hh0, b_ih0, b_hh0,
        W_ih1, W_hh1, b_ih1, b_hh1, W_fc, b_fc, out);
}

// round 3
// speedup vs baseline: 1.0119x; 1.0119x over previous
#include <cuda_runtime.h>
#include <cstddef>

#define BATCH 256
#define SEQ   512
#define DIN   64
#define HID   512
#define GRIDN 128
#define NTH   256

#define TM 64
#define TN 64
#define TN2 (2*TN)          // duplicated-weight row width
#define KA_PER 144          // 576 / 4
#define KB_PER 256          // 1024 / 4
#define CHUNK 16
#define NC_A (KA_PER / CHUNK)   // 9
#define NC_B (KB_PER / CHUNK)   // 16

// SMEM: Wa_dup 144*128*4 + Wb_dup 256*128*4 + staging 2*16*64*4 = 212,992 B
#define SMEM_BYTES ((KA_PER*TN2 + KB_PER*TN2 + 2*CHUNK*TM) * 4)

// ---------------- cross-CTA state (static scratch; allocation-free) ----------------
__device__ float g_H1[BATCH * HID];
__device__ float g_H2[BATCH * HID];
__device__ float g_P[4 * BATCH * HID];

struct __align__(128) BarLine { unsigned v; unsigned pad[31]; };
__device__ BarLine g_bar_cnt;       // own 128B line
__device__ BarLine g_bar_gen;       // own 128B line

__device__ __forceinline__ void grid_sync() {
    __syncthreads();
    if (threadIdx.x == 0) {
        unsigned gen = *(volatile unsigned*)&g_bar_gen.v;
        __threadfence();
        if (atomicAdd(&g_bar_cnt.v, 1u) == GRIDN - 1u) {
            g_bar_cnt.v = 0u;
            __threadfence();
            *(volatile unsigned*)&g_bar_gen.v = gen + 1u;
        } else {
            while (*(volatile unsigned*)&g_bar_gen.v == gen) { __nanosleep(32); }
        }
        __threadfence();
    }
    __syncthreads();
}

// ---------------- f32x2 helpers ----------------
__device__ __forceinline__ void fma2(unsigned long long& d,
                                     unsigned long long a, unsigned long long b) {
    asm("fma.rn.f32x2 %0, %1, %2, %0;" : "+l"(d) : "l"(a), "l"(b));
}
__device__ __forceinline__ float2 unpk(unsigned long long v) {
    float2 r;
    asm("mov.b64 {%0, %1}, %2;" : "=f"(r.x), "=f"(r.y) : "l"(v));
    return r;
}

__global__ void __launch_bounds__(NTH, 1) rnn_persistent(
    const float* __restrict__ x,
    const float* __restrict__ W_ih0, const float* __restrict__ W_hh0,
    const float* __restrict__ b_ih0, const float* __restrict__ b_hh0,
    const float* __restrict__ W_ih1, const float* __restrict__ W_hh1,
    const float* __restrict__ b_ih1, const float* __restrict__ b_hh1,
    const float* __restrict__ W_fc,  const float* __restrict__ b_fc,
    float* __restrict__ out)
{
    const int tid  = threadIdx.x;
    const int bid  = blockIdx.x;
    const int ks   = bid & 3;        // K-split index 0..3
    const int tile = bid >> 2;       // 0..31
    const int mt   = tile >> 3;      // 0..3
    const int nt   = tile & 7;       // 0..7
    const int m0   = mt * TM;
    const int n0   = nt * TN;

    extern __shared__ float smem[];
    float* Ws_a = smem;                       // [KA_PER][TN2] duplicated
    float* Ws_b = Ws_a + KA_PER * TN2;        // [KB_PER][TN2] duplicated
    float* As   = Ws_b + KB_PER * TN2;        // [2][CHUNK][TM]

    // ---------- one-time: weight slices -> SMEM, duplicated for f32x2 ----------
    {
        const int kb = ks * KA_PER;
        for (int idx = tid; idx < KA_PER * TN; idx += NTH) {
            int n  = idx / KA_PER;
            int k  = idx - n * KA_PER;
            int kg = kb + k;
            float v = (kg < DIN) ? W_ih0[(n0 + n) * DIN + kg]
                                 : W_hh0[(n0 + n) * HID + (kg - DIN)];
            Ws_a[k * TN2 + 2 * n]     = v;
            Ws_a[k * TN2 + 2 * n + 1] = v;
        }
        const int kbb = ks * KB_PER;
        for (int idx = tid; idx < KB_PER * TN; idx += NTH) {
            int n  = idx / KB_PER;
            int k  = idx - n * KB_PER;
            int kg = kbb + k;
            float v = (kg < HID) ? W_ih1[(n0 + n) * HID + kg]
                                 : W_hh1[(n0 + n) * HID + (kg - HID)];
            Ws_b[k * TN2 + 2 * n]     = v;
            Ws_b[k * TN2 + 2 * n + 1] = v;
        }
    }
    // ---------- zero hidden states ----------
    {
        const int per  = (BATCH * HID) / GRIDN;  // 1024
        const int base = bid * per;
        for (int i = tid; i < per; i += NTH) {
            g_H1[base + i] = 0.f;
            g_H2[base + i] = 0.f;
        }
    }
    grid_sync();

    const int tm   = tid & 15;   // m-quad
    const int tn   = tid >> 4;   // n-quad
    const int mm   = tid & 63;   // staging: row
    const int kq   = tid >> 6;   // staging: k-quad (0..3)
    const int m_ld = m0 + mm;

    for (int t = 0; t < SEQ; ++t) {
        // ============================ phase A: compute ============================
        {
            unsigned long long acc[2][4];
            #pragma unroll
            for (int i = 0; i < 2; i++)
                #pragma unroll
                for (int j = 0; j < 4; j++) acc[i][j] = 0ull;

            const int kb = ks * KA_PER;
            auto ldA = [&](int c) -> float4 {
                int kg = kb + c * CHUNK + kq * 4;
                if (kg < DIN)
                    return *(const float4*)(x + ((size_t)m_ld * SEQ + t) * DIN + kg);
                return __ldcg((const float4*)(g_H1 + (size_t)m_ld * HID + (kg - DIN)));
            };
            float4 v = ldA(0);
            for (int c = 0; c < NC_A; ++c) {
                float* dst = As + (c & 1) * (CHUNK * TM);
                dst[(kq * 4 + 0) * TM + mm] = v.x;
                dst[(kq * 4 + 1) * TM + mm] = v.y;
                dst[(kq * 4 + 2) * TM + mm] = v.z;
                dst[(kq * 4 + 3) * TM + mm] = v.w;
                __syncthreads();
                v = ldA((c + 1 < NC_A) ? c + 1 : 0);   // prefetch (dummy wrap on last)
                const float* Ab = As + (c & 1) * (CHUNK * TM);
                const float* Wb = Ws_a + c * CHUNK * TN2;
                #pragma unroll
                for (int kk = 0; kk < CHUNK; ++kk) {
                    ulonglong2 ap = *(const ulonglong2*)(Ab + kk * TM + tm * 4);
                    ulonglong2 w01 = *(const ulonglong2*)(Wb + kk * TN2 + tn * 8);
                    ulonglong2 w23 = *(const ulonglong2*)(Wb + kk * TN2 + tn * 8 + 4);
                    fma2(acc[0][0], ap.x, w01.x); fma2(acc[1][0], ap.y, w01.x);
                    fma2(acc[0][1], ap.x, w01.y); fma2(acc[1][1], ap.y, w01.y);
                    fma2(acc[0][2], ap.x, w23.x); fma2(acc[1][2], ap.y, w23.x);
                    fma2(acc[0][3], ap.x, w23.y); fma2(acc[1][3], ap.y, w23.y);
                }
                __syncthreads();
            }
            float* P = g_P + (size_t)ks * BATCH * HID;
            #pragma unroll
            for (int i = 0; i < 2; i++) {   // m-pair i -> rows tm*4+2i, tm*4+2i+1
                float2 n0v = unpk(acc[i][0]);
                float2 n1v = unpk(acc[i][1]);
                float2 n2v = unpk(acc[i][2]);
                float2 n3v = unpk(acc[i][3]);
                int m = m0 + tm * 4 + 2 * i;
                *(float4*)(P + (size_t)m * HID + n0 + tn * 4) =
                    make_float4(n0v.x, n1v.x, n2v.x, n3v.x);
                *(float4*)(P + (size_t)(m + 1) * HID + n0 + tn * 4) =
                    make_float4(n0v.y, n1v.y, n2v.y, n3v.y);
            }
        }
        grid_sync();
        // ============================ reduce A -> H1 ============================
        {
            int o = (bid << 10) + (tid << 2);
            int b = o >> 9;
            int n = o & (HID - 1);
            const float* Pb = g_P + (size_t)b * HID + n;
            float4 p0 = __ldcg((const float4*)(Pb + (size_t)0 * BATCH * HID));
            float4 p1 = __ldcg((const float4*)(Pb + (size_t)1 * BATCH * HID));
            float4 p2 = __ldcg((const float4*)(Pb + (size_t)2 * BATCH * HID));
            float4 p3 = __ldcg((const float4*)(Pb + (size_t)3 * BATCH * HID));
            float4 bi = *(const float4*)(b_ih0 + n);
            float4 bh = *(const float4*)(b_hh0 + n);
            float4 h;
            h.x = tanhf(bi.x + bh.x + p0.x + p1.x + p2.x + p3.x);
            h.y = tanhf(bi.y + bh.y + p0.y + p1.y + p2.y + p3.y);
            h.z = tanhf(bi.z + bh.z + p0.z + p1.z + p2.z + p3.z);
            h.w = tanhf(bi.w + bh.w + p0.w + p1.w + p2.w + p3.w);
            *(float4*)(g_H1 + (size_t)b * HID + n) = h;
        }
        grid_sync();
        // ============================ phase B: compute ============================
        {
            unsigned long long acc[2][4];
            #pragma unroll
            for (int i = 0; i < 2; i++)
                #pragma unroll
                for (int j = 0; j < 4; j++) acc[i][j] = 0ull;

            const int kb = ks * KB_PER;
            auto ldB = [&](int c) -> float4 {
                int kg = kb + c * CHUNK + kq * 4;
                const float* src = (kg < HID)
                    ? (g_H1 + (size_t)m_ld * HID + kg)
                    : (g_H2 + (size_t)m_ld * HID + (kg - HID));
                return __ldcg((const float4*)src);
            };
            float4 v = ldB(0);
            for (int c = 0; c < NC_B; ++c) {
                float* dst = As + (c & 1) * (CHUNK * TM);
                dst[(kq * 4 + 0) * TM + mm] = v.x;
                dst[(kq * 4 + 1) * TM + mm] = v.y;
                dst[(kq * 4 + 2) * TM + mm] = v.z;
                dst[(kq * 4 + 3) * TM + mm] = v.w;
                __syncthreads();
                v = ldB((c + 1 < NC_B) ? c + 1 : 0);
                const float* Ab = As + (c & 1) * (CHUNK * TM);
                const float* Wb = Ws_b + c * CHUNK * TN2;
                #pragma unroll
                for (int kk = 0; kk < CHUNK; ++kk) {
                    ulonglong2 ap = *(const ulonglong2*)(Ab + kk * TM + tm * 4);
                    ulonglong2 w01 = *(const ulonglong2*)(Wb + kk * TN2 + tn * 8);
                    ulonglong2 w23 = *(const ulonglong2*)(Wb + kk * TN2 + tn * 8 + 4);
                    fma2(acc[0][0], ap.x, w01.x); fma2(acc[1][0], ap.y, w01.x);
                    fma2(acc[0][1], ap.x, w01.y); fma2(acc[1][1], ap.y, w01.y);
                    fma2(acc[0][2], ap.x, w23.x); fma2(acc[1][2], ap.y, w23.x);
                    fma2(acc[0][3], ap.x, w23.y); fma2(acc[1][3], ap.y, w23.y);
                }
                __syncthreads();
            }
            float* P = g_P + (size_t)ks * BATCH * HID;
            #pragma unroll
            for (int i = 0; i < 2; i++) {
                float2 n0v = unpk(acc[i][0]);
                float2 n1v = unpk(acc[i][1]);
                float2 n2v = unpk(acc[i][2]);
                float2 n3v = unpk(acc[i][3]);
                int m = m0 + tm * 4 + 2 * i;
                *(float4*)(P + (size_t)m * HID + n0 + tn * 4) =
                    make_float4(n0v.x, n1v.x, n2v.x, n3v.x);
                *(float4*)(P + (size_t)(m + 1) * HID + n0 + tn * 4) =
                    make_float4(n0v.y, n1v.y, n2v.y, n3v.y);
            }
        }
        grid_sync();
        // ============================ reduce B -> H2 ============================
        {
            int o = (bid << 10) + (tid << 2);
            int b = o >> 9;
            int n = o & (HID - 1);
            const float* Pb = g_P + (size_t)b * HID + n;
            float4 p0 = __ldcg((const float4*)(Pb + (size_t)0 * BATCH * HID));
            float4 p1 = __ldcg((const float4*)(Pb + (size_t)1 * BATCH * HID));
            float4 p2 = __ldcg((const float4*)(Pb + (size_t)2 * BATCH * HID));
            float4 p3 = __ldcg((const float4*)(Pb + (size_t)3 * BATCH * HID));
            float4 bi = *(const float4*)(b_ih1 + n);
            float4 bh = *(const float4*)(b_hh1 + n);
            float4 h;
            h.x = tanhf(bi.x + bh.x + p0.x + p1.x + p2.x + p3.x);
            h.y = tanhf(bi.y + bh.y + p0.y + p1.y + p2.y + p3.y);
            h.z = tanhf(bi.z + bh.z + p0.z + p1.z + p2.z + p3.z);
            h.w = tanhf(bi.w + bh.w + p0.w + p1.w + p2.w + p3.w);
            *(float4*)(g_H2 + (size_t)b * HID + n) = h;
        }
        grid_sync();
    }

    // ============================ final FC: out[b] = H2[b,:] . W_fc + b_fc ============================
    __shared__ float red[8];
    for (int r = 0; r < 2; ++r) {
        int b = bid * 2 + r;
        float s = 0.f;
        for (int h = tid; h < HID; h += NTH)
            s += __ldcg(g_H2 + (size_t)b * HID + h) * W_fc[h];
        #pragma unroll
        for (int off = 16; off; off >>= 1)
            s += __shfl_down_sync(0xffffffffu, s, off);
        if ((tid & 31) == 0) red[tid >> 5] = s;
        __syncthreads();
        if (tid == 0) {
            float tot = b_fc[0];
            #pragma unroll
            for (int w = 0; w < 8; w++) tot += red[w];
            out[b] = tot;
        }
        __syncthreads();
    }
}

extern "C" void kernel_launch(void* const* d_in, const int* in_sizes, int n_in,
                              void* d_out, int out_size) {
    (void)in_sizes; (void)n_in; (void)out_size;
    const float* x     = (const float*)d_in[0];
    const float* W_ih0 = (const float*)d_in[1];
    const float* W_hh0 = (const float*)d_in[2];
    const float* b_ih0 = (const float*)d_in[3];
    const float* b_hh0 = (const float*)d_in[4];
    const float* W_ih1 = (const float*)d_in[5];
    const float* W_hh1 = (const float*)d_in[6];
    const float* b_ih1 = (const float*)d_in[7];
    const float* b_hh1 = (const float*)d_in[8];
    const float* W_fc  = (const float*)d_in[9];
    const float* b_fc  = (const float*)d_in[10];
    float* out = (float*)d_out;

    cudaFuncSetAttribute(rnn_persistent,
                         cudaFuncAttributeMaxDynamicSharedMemorySize, SMEM_BYTES);
    rnn_persistent<<<GRIDN, NTH, SMEM_BYTES>>>(
        x, W_ih0, W_hh0, b_ih0, b_hh0,
        W_ih1, W_hh1, b_ih1, b_hh1, W_fc, b_fc, out);
}

// round 4
// speedup vs baseline: 1.3651x; 1.3490x over previous
#include <cuda_runtime.h>
#include <cstddef>

#define BATCH 256
#define SEQ   512
#define DIN   64
#define HID   512
#define GRIDN 128
#define NTH   256

#define TM 64
#define TN 64
#define KA_PER 144          // 576 / 4
#define KB_PER 256          // 1024 / 4
#define CHUNK 16
#define NC_A (KA_PER / CHUNK)   // 9
#define NC_B (KB_PER / CHUNK)   // 16

#define SMEM_BYTES 122880   // > 113.5KB -> forces 1 CTA/SM; actual use ~110.6KB

// ---------------- cross-CTA state (static scratch; allocation-free) ----------------
__device__ float g_H1[2][BATCH * HID];
__device__ float g_H2[2][BATCH * HID];
__device__ float g_PA[4 * BATCH * HID];
__device__ float g_PB[4 * BATCH * HID];

struct __align__(128) Line { unsigned v; unsigned pad[31]; };
__device__ Line g_leaf[8];
__device__ Line g_root;
__device__ Line g_gen;

// 2-level tree barrier: 8 leaves x 16 CTAs, then root x 8.
__device__ __forceinline__ void grid_sync(int leaf) {
    __syncthreads();
    if (threadIdx.x == 0) {
        unsigned gen = *(volatile unsigned*)&g_gen.v;
        __threadfence();
        if (atomicAdd(&g_leaf[leaf].v, 1u) == 15u) {
            g_leaf[leaf].v = 0u;
            __threadfence();                 // reset visible before gen bump chain
            if (atomicAdd(&g_root.v, 1u) == 7u) {
                g_root.v = 0u;
                __threadfence();
                *(volatile unsigned*)&g_gen.v = gen + 1u;
            } else {
                while (*(volatile unsigned*)&g_gen.v == gen) __nanosleep(16);
            }
        } else {
            while (*(volatile unsigned*)&g_gen.v == gen) __nanosleep(16);
        }
        __threadfence();
    }
    __syncthreads();
}

__global__ void __launch_bounds__(NTH, 1) rnn_persistent(
    const float* __restrict__ x,
    const float* __restrict__ W_ih0, const float* __restrict__ W_hh0,
    const float* __restrict__ b_ih0, const float* __restrict__ b_hh0,
    const float* __restrict__ W_ih1, const float* __restrict__ W_hh1,
    const float* __restrict__ b_ih1, const float* __restrict__ b_hh1,
    const float* __restrict__ W_fc,  const float* __restrict__ b_fc,
    float* __restrict__ out)
{
    const int tid  = threadIdx.x;
    const int bid  = blockIdx.x;
    const int leaf = bid & 7;
    const int ks   = bid & 3;        // K-split index 0..3
    const int tile = bid >> 2;       // 0..31
    const int mt   = tile >> 3;      // 0..3
    const int nt   = tile & 7;       // 0..7
    const int m0   = mt * TM;
    const int n0   = nt * TN;

    extern __shared__ float smem[];
    float* Ws_a = smem;                      // [KA_PER][TN]
    float* Ws_b = Ws_a + KA_PER * TN;        // [KB_PER][TN]
    float* As   = Ws_b + KB_PER * TN;        // [2][CHUNK][TM]

    // ---------- one-time: weight slices -> SMEM ----------
    {
        const int kb = ks * KA_PER;
        for (int idx = tid; idx < KA_PER * TN; idx += NTH) {
            int n  = idx / KA_PER;
            int k  = idx - n * KA_PER;
            int kg = kb + k;
            Ws_a[k * TN + n] = (kg < DIN) ? W_ih0[(n0 + n) * DIN + kg]
                                          : W_hh0[(n0 + n) * HID + (kg - DIN)];
        }
        const int kbb = ks * KB_PER;
        for (int idx = tid; idx < KB_PER * TN; idx += NTH) {
            int n  = idx / KB_PER;
            int k  = idx - n * KB_PER;
            int kg = kbb + k;
            Ws_b[k * TN + n] = (kg < HID) ? W_ih1[(n0 + n) * HID + kg]
                                          : W_hh1[(n0 + n) * HID + (kg - HID)];
        }
    }
    // ---------- zero the t=-1 buffers: g_H1[1], g_H2[1] ----------
    {
        const int per  = (BATCH * HID) / GRIDN;  // 1024
        const int base = bid * per;
        for (int i = tid; i < per; i += NTH) {
            g_H1[1][base + i] = 0.f;
            g_H2[1][base + i] = 0.f;
        }
    }
    grid_sync(leaf);

    const int tm   = tid & 15;   // m-quad
    const int tn   = tid >> 4;   // n-quad
    const int mm   = tid & 63;   // staging: row
    const int kq   = tid >> 6;   // staging: k-quad (0..3)
    const int m_ld = m0 + mm;

    // reduce-role constants (n fixed per thread -> hoist bias loads)
    const int ro = (bid << 10) + (tid << 2);
    const int rb = ro >> 9;
    const int rn = ro & (HID - 1);
    float4 biasA, biasB;
    {
        float4 bi = *(const float4*)(b_ih0 + rn);
        float4 bh = *(const float4*)(b_hh0 + rn);
        biasA = make_float4(bi.x + bh.x, bi.y + bh.y, bi.z + bh.z, bi.w + bh.w);
        bi = *(const float4*)(b_ih1 + rn);
        bh = *(const float4*)(b_hh1 + rn);
        biasB = make_float4(bi.x + bh.x, bi.y + bh.y, bi.z + bh.z, bi.w + bh.w);
    }

    // -------- phase-A compute (step tA): partials -> g_PA; reads h1p --------
    auto phaseA = [&](int tA, const float* __restrict__ h1p) {
        float acc[4][4];
        #pragma unroll
        for (int i = 0; i < 4; i++)
            #pragma unroll
            for (int j = 0; j < 4; j++) acc[i][j] = 0.f;

        const int kb = ks * KA_PER;
        auto ldA = [&](int c) -> float4 {
            int kg = kb + c * CHUNK + kq * 4;
            if (kg < DIN)
                return *(const float4*)(x + ((size_t)m_ld * SEQ + tA) * DIN + kg);
            return __ldcg((const float4*)(h1p + (size_t)m_ld * HID + (kg - DIN)));
        };
        float4 v = ldA(0);
        for (int c = 0; c < NC_A; ++c) {
            float* dst = As + (c & 1) * (CHUNK * TM);
            dst[(kq * 4 + 0) * TM + mm] = v.x;
            dst[(kq * 4 + 1) * TM + mm] = v.y;
            dst[(kq * 4 + 2) * TM + mm] = v.z;
            dst[(kq * 4 + 3) * TM + mm] = v.w;
            __syncthreads();
            v = ldA((c + 1 < NC_A) ? c + 1 : 0);
            const float* Ab = As + (c & 1) * (CHUNK * TM);
            const float* Wb = Ws_a + c * CHUNK * TN;
            #pragma unroll
            for (int kk = 0; kk < CHUNK; ++kk) {
                float4 av = *(const float4*)(Ab + kk * TM + tm * 4);
                float4 wv = *(const float4*)(Wb + kk * TN + tn * 4);
                acc[0][0] = fmaf(av.x, wv.x, acc[0][0]);
                acc[0][1] = fmaf(av.x, wv.y, acc[0][1]);
                acc[0][2] = fmaf(av.x, wv.z, acc[0][2]);
                acc[0][3] = fmaf(av.x, wv.w, acc[0][3]);
                acc[1][0] = fmaf(av.y, wv.x, acc[1][0]);
                acc[1][1] = fmaf(av.y, wv.y, acc[1][1]);
                acc[1][2] = fmaf(av.y, wv.z, acc[1][2]);
                acc[1][3] = fmaf(av.y, wv.w, acc[1][3]);
                acc[2][0] = fmaf(av.z, wv.x, acc[2][0]);
                acc[2][1] = fmaf(av.z, wv.y, acc[2][1]);
                acc[2][2] = fmaf(av.z, wv.z, acc[2][2]);
                acc[2][3] = fmaf(av.z, wv.w, acc[2][3]);
                acc[3][0] = fmaf(av.w, wv.x, acc[3][0]);
                acc[3][1] = fmaf(av.w, wv.y, acc[3][1]);
                acc[3][2] = fmaf(av.w, wv.z, acc[3][2]);
                acc[3][3] = fmaf(av.w, wv.w, acc[3][3]);
            }
            __syncthreads();
        }
        float* P = g_PA + (size_t)ks * BATCH * HID;
        #pragma unroll
        for (int i = 0; i < 4; i++) {
            int m = m0 + tm * 4 + i;
            *(float4*)(P + (size_t)m * HID + n0 + tn * 4) =
                make_float4(acc[i][0], acc[i][1], acc[i][2], acc[i][3]);
        }
    };

    // -------- phase-B compute (step tB = t-1): partials -> g_PB; reads h1p,h2p --------
    auto phaseB = [&](const float* __restrict__ h1p, const float* __restrict__ h2p) {
        float acc[4][4];
        #pragma unroll
        for (int i = 0; i < 4; i++)
            #pragma unroll
            for (int j = 0; j < 4; j++) acc[i][j] = 0.f;

        const int kb = ks * KB_PER;
        auto ldB = [&](int c) -> float4 {
            int kg = kb + c * CHUNK + kq * 4;
            const float* src = (kg < HID)
                ? (h1p + (size_t)m_ld * HID + kg)
                : (h2p + (size_t)m_ld * HID + (kg - HID));
            return __ldcg((const float4*)src);
        };
        float4 v = ldB(0);
        for (int c = 0; c < NC_B; ++c) {
            float* dst = As + (c & 1) * (CHUNK * TM);
            dst[(kq * 4 + 0) * TM + mm] = v.x;
            dst[(kq * 4 + 1) * TM + mm] = v.y;
            dst[(kq * 4 + 2) * TM + mm] = v.z;
            dst[(kq * 4 + 3) * TM + mm] = v.w;
            __syncthreads();
            v = ldB((c + 1 < NC_B) ? c + 1 : 0);
            const float* Ab = As + (c & 1) * (CHUNK * TM);
            const float* Wb = Ws_b + c * CHUNK * TN;
            #pragma unroll
            for (int kk = 0; kk < CHUNK; ++kk) {
                float4 av = *(const float4*)(Ab + kk * TM + tm * 4);
                float4 wv = *(const float4*)(Wb + kk * TN + tn * 4);
                acc[0][0] = fmaf(av.x, wv.x, acc[0][0]);
                acc[0][1] = fmaf(av.x, wv.y, acc[0][1]);
                acc[0][2] = fmaf(av.x, wv.z, acc[0][2]);
                acc[0][3] = fmaf(av.x, wv.w, acc[0][3]);
                acc[1][0] = fmaf(av.y, wv.x, acc[1][0]);
                acc[1][1] = fmaf(av.y, wv.y, acc[1][1]);
                acc[1][2] = fmaf(av.y, wv.z, acc[1][2]);
                acc[1][3] = fmaf(av.y, wv.w, acc[1][3]);
                acc[2][0] = fmaf(av.z, wv.x, acc[2][0]);
                acc[2][1] = fmaf(av.z, wv.y, acc[2][1]);
                acc[2][2] = fmaf(av.z, wv.z, acc[2][2]);
                acc[2][3] = fmaf(av.z, wv.w, acc[2][3]);
                acc[3][0] = fmaf(av.w, wv.x, acc[3][0]);
                acc[3][1] = fmaf(av.w, wv.y, acc[3][1]);
                acc[3][2] = fmaf(av.w, wv.z, acc[3][2]);
                acc[3][3] = fmaf(av.w, wv.w, acc[3][3]);
            }
            __syncthreads();
        }
        float* P = g_PB + (size_t)ks * BATCH * HID;
        #pragma unroll
        for (int i = 0; i < 4; i++) {
            int m = m0 + tm * 4 + i;
            *(float4*)(P + (size_t)m * HID + n0 + tn * 4) =
                make_float4(acc[i][0], acc[i][1], acc[i][2], acc[i][3]);
        }
    };

    auto reduce4 = [&](const float* __restrict__ Pbase, const float4& bias,
                       float* __restrict__ dst) {
        const float* Pb = Pbase + (size_t)rb * HID + rn;
        float4 p0 = __ldcg((const float4*)(Pb + (size_t)0 * BATCH * HID));
        float4 p1 = __ldcg((const float4*)(Pb + (size_t)1 * BATCH * HID));
        float4 p2 = __ldcg((const float4*)(Pb + (size_t)2 * BATCH * HID));
        float4 p3 = __ldcg((const float4*)(Pb + (size_t)3 * BATCH * HID));
        float4 h;
        h.x = tanhf(bias.x + p0.x + p1.x + p2.x + p3.x);
        h.y = tanhf(bias.y + p0.y + p1.y + p2.y + p3.y);
        h.z = tanhf(bias.z + p0.z + p1.z + p2.z + p3.z);
        h.w = tanhf(bias.w + p0.w + p1.w + p2.w + p3.w);
        __stcg((float4*)(dst + (size_t)rb * HID + rn), h);
    };

    // ============================ main pipelined loop ============================
    // iter t: compute A(t) [needs h1(t-1)] and B(t-1) [needs h1(t-1), h2(t-2)];
    //         reduce -> publish h1(t), h2(t-1).
    for (int t = 0; t < SEQ; ++t) {
        const float* h1p = g_H1[(t + 1) & 1];   // h1(t-1)
        const float* h2p = g_H2[t & 1];         // h2(t-2)
        float*       h1w = g_H1[t & 1];         // h1(t)
        float*       h2w = g_H2[(t + 1) & 1];   // h2(t-1)

        phaseA(t, h1p);
        if (t > 0) phaseB(h1p, h2p);
        grid_sync(leaf);

        reduce4(g_PA, biasA, h1w);
        if (t > 0) reduce4(g_PB, biasB, h2w);
        grid_sync(leaf);
    }
    // epilogue: B(511) — h1(511) in g_H1[1], h2(510) in g_H2[0]
    phaseB(g_H1[1], g_H2[0]);
    grid_sync(leaf);
    reduce4(g_PB, biasB, g_H2[1]);             // h2(511) -> g_H2[1]
    grid_sync(leaf);

    // ============================ final FC ============================
    const float* h2f = g_H2[1];
    __shared__ float red[8];
    for (int r = 0; r < 2; ++r) {
        int b = bid * 2 + r;
        float s = 0.f;
        for (int h = tid; h < HID; h += NTH)
            s += __ldcg(h2f + (size_t)b * HID + h) * W_fc[h];
        #pragma unroll
        for (int off = 16; off; off >>= 1)
            s += __shfl_down_sync(0xffffffffu, s, off);
        if ((tid & 31) == 0) red[tid >> 5] = s;
        __syncthreads();
        if (tid == 0) {
            float tot = b_fc[0];
            #pragma unroll
            for (int w = 0; w < 8; w++) tot += red[w];
            out[b] = tot;
        }
        __syncthreads();
    }
}

extern "C" void kernel_launch(void* const* d_in, const int* in_sizes, int n_in,
                              void* d_out, int out_size) {
    (void)in_sizes; (void)n_in; (void)out_size;
    const float* x     = (const float*)d_in[0];
    const float* W_ih0 = (const float*)d_in[1];
    const float* W_hh0 = (const float*)d_in[2];
    const float* b_ih0 = (const float*)d_in[3];
    const float* b_hh0 = (const float*)d_in[4];
    const float* W_ih1 = (const float*)d_in[5];
    const float* W_hh1 = (const float*)d_in[6];
    const float* b_ih1 = (const float*)d_in[7];
    const float* b_hh1 = (const float*)d_in[8];
    const float* W_fc  = (const float*)d_in[9];
    const float* b_fc  = (const float*)d_in[10];
    float* out = (float*)d_out;

    cudaFuncSetAttribute(rnn_persistent,
                         cudaFuncAttributeMaxDynamicSharedMemorySize, SMEM_BYTES);
    rnn_persistent<<<GRIDN, NTH, SMEM_BYTES>>>(
        x, W_ih0, W_hh0, b_ih0, b_hh0,
        W_ih1, W_hh1, b_ih1, b_hh1, W_fc, b_fc, out);
}

// round 5
// speedup vs baseline: 1.3743x; 1.0067x over previous
#include <cuda_runtime.h>
#include <cuda_bf16.h>
#include <cstddef>

#define BATCH 256
#define SEQ   512
#define DIN   64
#define HID   512
#define GRIDN 128
#define NTH   256

#define TM 64
#define TN 64
#define KA_PER 144          // 576 / 4
#define KB_PER 256          // 1024 / 4

#define STRIDE 264          // smem row stride (bf16 elems): words%32==4 -> conflict-free frags
#define TILE_ELEMS (64 * STRIDE)
#define OFF_WA_HI 0
#define OFF_WA_LO (1 * TILE_ELEMS)
#define OFF_WB_HI (2 * TILE_ELEMS)
#define OFF_WB_LO (3 * TILE_ELEMS)
#define OFF_A_HI  (4 * TILE_ELEMS)
#define OFF_A_LO  (5 * TILE_ELEMS)
#define SMEM_BYTES (6 * TILE_ELEMS * 2)   // 202,752 B -> 1 CTA/SM

typedef unsigned long long ull;

// ---------------- cross-CTA state (static scratch; allocation-free) ----------------
__device__ __nv_bfloat16 g_Xhi[BATCH * SEQ * DIN];
__device__ __nv_bfloat16 g_Xlo[BATCH * SEQ * DIN];
__device__ __nv_bfloat16 g_H1hi[2][BATCH * HID], g_H1lo[2][BATCH * HID];
__device__ __nv_bfloat16 g_H2hi[2][BATCH * HID], g_H2lo[2][BATCH * HID];
__device__ float g_PA[8ull * BATCH * HID];
__device__ float g_PB[8ull * BATCH * HID];

struct __align__(128) Line { unsigned v; unsigned pad[31]; };
__device__ Line g_leaf[8];
__device__ Line g_root;
__device__ Line g_gen;

__device__ __forceinline__ void grid_sync(int leaf) {
    __syncthreads();
    if (threadIdx.x == 0) {
        unsigned gen = *(volatile unsigned*)&g_gen.v;
        __threadfence();
        if (atomicAdd(&g_leaf[leaf].v, 1u) == 15u) {
            g_leaf[leaf].v = 0u;
            __threadfence();
            if (atomicAdd(&g_root.v, 1u) == 7u) {
                g_root.v = 0u;
                __threadfence();
                *(volatile unsigned*)&g_gen.v = gen + 1u;
            } else {
                while (*(volatile unsigned*)&g_gen.v == gen) __nanosleep(16);
            }
        } else {
            while (*(volatile unsigned*)&g_gen.v == gen) __nanosleep(16);
        }
        __threadfence();
    }
    __syncthreads();
}

// ---------------- mma.sync m16n8k16 bf16 (HMMA) ----------------
__device__ __forceinline__ void mma16816(float* c, const unsigned* a, const unsigned* b) {
    asm volatile(
        "mma.sync.aligned.m16n8k16.row.col.f32.bf16.bf16.f32 "
        "{%0,%1,%2,%3}, {%4,%5,%6,%7}, {%8,%9}, {%0,%1,%2,%3};"
        : "+f"(c[0]), "+f"(c[1]), "+f"(c[2]), "+f"(c[3])
        : "r"(a[0]), "r"(a[1]), "r"(a[2]), "r"(a[3]), "r"(b[0]), "r"(b[1]));
}

__device__ __forceinline__ void split_bf16(float v, __nv_bfloat16& hi, __nv_bfloat16& lo) {
    hi = __float2bfloat16_rn(v);
    lo = __float2bfloat16_rn(v - __bfloat162float(hi));
}

__global__ void __launch_bounds__(NTH, 1) rnn_hmma(
    const float* __restrict__ x,
    const float* __restrict__ W_ih0, const float* __restrict__ W_hh0,
    const float* __restrict__ b_ih0, const float* __restrict__ b_hh0,
    const float* __restrict__ W_ih1, const float* __restrict__ W_hh1,
    const float* __restrict__ b_ih1, const float* __restrict__ b_hh1,
    const float* __restrict__ W_fc,  const float* __restrict__ b_fc,
    float* __restrict__ out)
{
    const int tid  = threadIdx.x;
    const int bid  = blockIdx.x;
    const int leaf = bid & 7;
    const int ks   = bid & 3;
    const int tile = bid >> 2;
    const int mt   = tile >> 3;
    const int nt   = tile & 7;
    const int m0   = mt * TM;
    const int n0   = nt * TN;

    extern __shared__ __nv_bfloat16 sm[];

    // ---------- one-time: split weight slices -> SMEM ----------
    {
        const int kb = ks * KA_PER;
        for (int idx = tid; idx < 64 * KA_PER; idx += NTH) {
            int n = idx / KA_PER, k = idx - n * KA_PER;
            int kg = kb + k;
            float v = (kg < DIN) ? W_ih0[(n0 + n) * DIN + kg]
                                 : W_hh0[(n0 + n) * HID + (kg - DIN)];
            __nv_bfloat16 hi, lo; split_bf16(v, hi, lo);
            sm[OFF_WA_HI + n * STRIDE + k] = hi;
            sm[OFF_WA_LO + n * STRIDE + k] = lo;
        }
        const int kbb = ks * KB_PER;
        for (int idx = tid; idx < 64 * KB_PER; idx += NTH) {
            int n = idx / KB_PER, k = idx - n * KB_PER;
            int kg = kbb + k;
            float v = (kg < HID) ? W_ih1[(n0 + n) * HID + kg]
                                 : W_hh1[(n0 + n) * HID + (kg - HID)];
            __nv_bfloat16 hi, lo; split_bf16(v, hi, lo);
            sm[OFF_WB_HI + n * STRIDE + k] = hi;
            sm[OFF_WB_LO + n * STRIDE + k] = lo;
        }
    }
    // ---------- one-time: pre-split x ----------
    {
        const int total = BATCH * SEQ * DIN;
        for (int i = (bid * NTH + tid) * 4; i < total; i += GRIDN * NTH * 4) {
            float4 v = *(const float4*)(x + i);
            __nv_bfloat16 h0,h1,h2,h3,l0,l1,l2,l3;
            split_bf16(v.x,h0,l0); split_bf16(v.y,h1,l1);
            split_bf16(v.z,h2,l2); split_bf16(v.w,h3,l3);
            *(__nv_bfloat162*)(g_Xhi + i)     = __halves2bfloat162(h0, h1);
            *(__nv_bfloat162*)(g_Xhi + i + 2) = __halves2bfloat162(h2, h3);
            *(__nv_bfloat162*)(g_Xlo + i)     = __halves2bfloat162(l0, l1);
            *(__nv_bfloat162*)(g_Xlo + i + 2) = __halves2bfloat162(l2, l3);
        }
    }
    // ---------- zero t=-1 states (buffer 1) ----------
    {
        const int per = (BATCH * HID) / GRIDN;   // 1024
        const int base = bid * per;
        __nv_bfloat162 z = __halves2bfloat162(__float2bfloat16(0.f), __float2bfloat16(0.f));
        for (int i = tid * 2; i < per; i += NTH * 2) {
            *(__nv_bfloat162*)(&g_H1hi[1][base + i]) = z;
            *(__nv_bfloat162*)(&g_H1lo[1][base + i]) = z;
            *(__nv_bfloat162*)(&g_H2hi[1][base + i]) = z;
            *(__nv_bfloat162*)(&g_H2lo[1][base + i]) = z;
        }
    }
    grid_sync(leaf);

    // ---------- roles ----------
    const int lane = tid & 31;
    const int wid  = tid >> 5;
    const int wm   = wid & 1;          // m-half
    const int wn   = (wid >> 1) & 1;   // n-half
    const int wk   = wid >> 2;         // k-half
    const int q    = lane >> 2;        // 0..7
    const int tg2  = (lane & 3) * 2;

    const int smm = tid & 63;          // staging row
    const int skq = tid >> 6;          // staging k-quad
    const int mg  = m0 + smm;

    // reduce role
    const int ro = (bid << 10) + (tid << 2);
    const int rb = ro >> 9;
    const int rn = ro & (HID - 1);
    float4 biasA, biasB;
    {
        float4 bi = *(const float4*)(b_ih0 + rn);
        float4 bh = *(const float4*)(b_hh0 + rn);
        biasA = make_float4(bi.x+bh.x, bi.y+bh.y, bi.z+bh.z, bi.w+bh.w);
        bi = *(const float4*)(b_ih1 + rn);
        bh = *(const float4*)(b_hh1 + rn);
        biasB = make_float4(bi.x+bh.x, bi.y+bh.y, bi.z+bh.z, bi.w+bh.w);
    }

    // ---------- staging ----------
    auto stageA = [&](int t, const __nv_bfloat16* h1phi, const __nv_bfloat16* h1plo) {
        #pragma unroll
        for (int j = 0; j < 9; ++j) {
            int kl = j * 16 + skq * 4;
            int kg = ks * KA_PER + kl;
            ull vh, vl;
            if (kg < DIN) {
                size_t off = (size_t)mg * (SEQ * DIN) + t * DIN + kg;
                vh = __ldcg((const ull*)(g_Xhi + off));
                vl = __ldcg((const ull*)(g_Xlo + off));
            } else {
                size_t off = (size_t)mg * HID + (kg - DIN);
                vh = __ldcg((const ull*)(h1phi + off));
                vl = __ldcg((const ull*)(h1plo + off));
            }
            *(ull*)(sm + OFF_A_HI + smm * STRIDE + kl) = vh;
            *(ull*)(sm + OFF_A_LO + smm * STRIDE + kl) = vl;
        }
    };
    auto stageB = [&](const __nv_bfloat16* h1phi, const __nv_bfloat16* h1plo,
                      const __nv_bfloat16* h2phi, const __nv_bfloat16* h2plo) {
        #pragma unroll
        for (int j = 0; j < 16; ++j) {
            int kl = j * 16 + skq * 4;
            int kg = ks * KB_PER + kl;
            ull vh, vl;
            if (kg < HID) {
                size_t off = (size_t)mg * HID + kg;
                vh = __ldcg((const ull*)(h1phi + off));
                vl = __ldcg((const ull*)(h1plo + off));
            } else {
                size_t off = (size_t)mg * HID + (kg - HID);
                vh = __ldcg((const ull*)(h2phi + off));
                vl = __ldcg((const ull*)(h2plo + off));
            }
            *(ull*)(sm + OFF_A_HI + smm * STRIDE + kl) = vh;
            *(ull*)(sm + OFF_A_LO + smm * STRIDE + kl) = vl;
        }
    };

    // ---------- one GEMM phase: 3-split HMMA; writes 8-slab partials ----------
    auto computePhase = [&](int offWhi, int offWlo, int ks0, int ks1, float* __restrict__ Pbase) {
        float acc[2][4][4];
        #pragma unroll
        for (int f = 0; f < 2; f++)
            #pragma unroll
            for (int g = 0; g < 4; g++)
                #pragma unroll
                for (int i = 0; i < 4; i++) acc[f][g][i] = 0.f;

        const __nv_bfloat16* Ah = sm + OFF_A_HI;
        const __nv_bfloat16* Al = sm + OFF_A_LO;
        const __nv_bfloat16* Wh = sm + offWhi;
        const __nv_bfloat16* Wl = sm + offWlo;
        const int r00 = wm * 32 + q;

        for (int kst = ks0; kst < ks1; ++kst) {
            const int kb = kst * 16 + tg2;
            unsigned ah[2][4], al[2][4], bh[4][2], bl[4][2];
            #pragma unroll
            for (int f = 0; f < 2; f++) {
                int r = (r00 + f * 16) * STRIDE;
                ah[f][0] = *(const unsigned*)(Ah + r + kb);
                ah[f][1] = *(const unsigned*)(Ah + r + 8 * STRIDE + kb);
                ah[f][2] = *(const unsigned*)(Ah + r + kb + 8);
                ah[f][3] = *(const unsigned*)(Ah + r + 8 * STRIDE + kb + 8);
                al[f][0] = *(const unsigned*)(Al + r + kb);
                al[f][1] = *(const unsigned*)(Al + r + 8 * STRIDE + kb);
                al[f][2] = *(const unsigned*)(Al + r + kb + 8);
                al[f][3] = *(const unsigned*)(Al + r + 8 * STRIDE + kb + 8);
            }
            #pragma unroll
            for (int g = 0; g < 4; g++) {
                int nr = (wn * 32 + g * 8 + q) * STRIDE;
                bh[g][0] = *(const unsigned*)(Wh + nr + kb);
                bh[g][1] = *(const unsigned*)(Wh + nr + kb + 8);
                bl[g][0] = *(const unsigned*)(Wl + nr + kb);
                bl[g][1] = *(const unsigned*)(Wl + nr + kb + 8);
            }
            #pragma unroll
            for (int f = 0; f < 2; f++)
                #pragma unroll
                for (int g = 0; g < 4; g++) {
                    mma16816(acc[f][g], ah[f], bh[g]);
                    mma16816(acc[f][g], al[f], bh[g]);
                    mma16816(acc[f][g], ah[f], bl[g]);
                }
        }
        const int slab = ks * 2 + wk;
        float* P = Pbase + (size_t)slab * (BATCH * HID);
        #pragma unroll
        for (int f = 0; f < 2; f++)
            #pragma unroll
            for (int g = 0; g < 4; g++) {
                int r = m0 + wm * 32 + f * 16 + q;
                int c = n0 + wn * 32 + g * 8 + tg2;
                *(float2*)(P + (size_t)r * HID + c) =
                    make_float2(acc[f][g][0], acc[f][g][1]);
                *(float2*)(P + (size_t)(r + 8) * HID + c) =
                    make_float2(acc[f][g][2], acc[f][g][3]);
            }
    };

    // ---------- reduce 8 slabs + tanh + split-store ----------
    auto reduce8 = [&](const float* __restrict__ Pbase, const float4& bias,
                       __nv_bfloat16* __restrict__ dhi, __nv_bfloat16* __restrict__ dlo) {
        const float* Pb = Pbase + (size_t)rb * HID + rn;
        float4 s = bias;
        #pragma unroll
        for (int sl = 0; sl < 8; sl++) {
            float4 p = __ldcg((const float4*)(Pb + (size_t)sl * BATCH * HID));
            s.x += p.x; s.y += p.y; s.z += p.z; s.w += p.w;
        }
        float h0 = tanhf(s.x), h1 = tanhf(s.y), h2 = tanhf(s.z), h3 = tanhf(s.w);
        __nv_bfloat16 hi0,hi1,hi2,hi3, lo0,lo1,lo2,lo3;
        split_bf16(h0,hi0,lo0); split_bf16(h1,hi1,lo1);
        split_bf16(h2,hi2,lo2); split_bf16(h3,hi3,lo3);
        __nv_bfloat162 ph0 = __halves2bfloat162(hi0, hi1), ph1 = __halves2bfloat162(hi2, hi3);
        __nv_bfloat162 pl0 = __halves2bfloat162(lo0, lo1), pl1 = __halves2bfloat162(lo2, lo3);
        uint2 uh, ul2;
        uh.x = *(unsigned*)&ph0; uh.y = *(unsigned*)&ph1;
        ul2.x = *(unsigned*)&pl0; ul2.y = *(unsigned*)&pl1;
        __stcg((uint2*)(dhi + (size_t)rb * HID + rn), uh);
        __stcg((uint2*)(dlo + (size_t)rb * HID + rn), ul2);
    };

    const int ksA0 = wk ? 5 : 0, ksA1 = wk ? 9 : 5;
    const int ksB0 = wk ? 8 : 0, ksB1 = wk ? 16 : 8;

    // ============================ main pipelined loop ============================
    for (int t = 0; t < SEQ; ++t) {
        const int pp = (t + 1) & 1, pc = t & 1;
        const __nv_bfloat16* h1phi = g_H1hi[pp]; const __nv_bfloat16* h1plo = g_H1lo[pp];
        const __nv_bfloat16* h2phi = g_H2hi[pc]; const __nv_bfloat16* h2plo = g_H2lo[pc];

        stageA(t, h1phi, h1plo);
        __syncthreads();
        computePhase(OFF_WA_HI, OFF_WA_LO, ksA0, ksA1, g_PA);
        __syncthreads();
        if (t > 0) {
            stageB(h1phi, h1plo, h2phi, h2plo);
            __syncthreads();
            computePhase(OFF_WB_HI, OFF_WB_LO, ksB0, ksB1, g_PB);
        }
        grid_sync(leaf);

        reduce8(g_PA, biasA, g_H1hi[pc], g_H1lo[pc]);
        if (t > 0) reduce8(g_PB, biasB, g_H2hi[pp], g_H2lo[pp]);
        grid_sync(leaf);
    }
    // epilogue: B(511): h1(511) in buf1, h2(510) in buf0 -> h2(511) in buf1
    stageB(g_H1hi[1], g_H1lo[1], g_H2hi[0], g_H2lo[0]);
    __syncthreads();
    computePhase(OFF_WB_HI, OFF_WB_LO, ksB0, ksB1, g_PB);
    grid_sync(leaf);
    reduce8(g_PB, biasB, g_H2hi[1], g_H2lo[1]);
    grid_sync(leaf);

    // ============================ final FC ============================
    static __shared__ float red[8];
    for (int r = 0; r < 2; ++r) {
        int b = bid * 2 + r;
        float s = 0.f;
        for (int h = tid * 2; h < HID; h += NTH * 2) {
            unsigned uh = __ldcg((const unsigned*)(&g_H2hi[1][(size_t)b * HID + h]));
            unsigned ul2 = __ldcg((const unsigned*)(&g_H2lo[1][(size_t)b * HID + h]));
            __nv_bfloat162 vh = *(__nv_bfloat162*)&uh;
            __nv_bfloat162 vl = *(__nv_bfloat162*)&ul2;
            float v0 = __bfloat162float(__low2bfloat16(vh)) + __bfloat162float(__low2bfloat16(vl));
            float v1 = __bfloat162float(__high2bfloat16(vh)) + __bfloat162float(__high2bfloat16(vl));
            s += v0 * W_fc[h] + v1 * W_fc[h + 1];
        }
        #pragma unroll
        for (int off = 16; off; off >>= 1)
            s += __shfl_down_sync(0xffffffffu, s, off);
        if ((tid & 31) == 0) red[tid >> 5] = s;
        __syncthreads();
        if (tid == 0) {
            float tot = b_fc[0];
            #pragma unroll
            for (int w = 0; w < 8; w++) tot += red[w];
            out[b] = tot;
        }
        __syncthreads();
    }
}

extern "C" void kernel_launch(void* const* d_in, const int* in_sizes, int n_in,
                              void* d_out, int out_size) {
    (void)in_sizes; (void)n_in; (void)out_size;
    const float* x     = (const float*)d_in[0];
    const float* W_ih0 = (const float*)d_in[1];
    const float* W_hh0 = (const float*)d_in[2];
    const float* b_ih0 = (const float*)d_in[3];
    const float* b_hh0 = (const float*)d_in[4];
    const float* W_ih1 = (const float*)d_in[5];
    const float* W_hh1 = (const float*)d_in[6];
    const float* b_ih1 = (const float*)d_in[7];
    const float* b_hh1 = (const float*)d_in[8];
    const float* W_fc  = (const float*)d_in[9];
    const float* b_fc  = (const float*)d_in[10];
    float* out = (float*)d_out;

    cudaFuncSetAttribute(rnn_hmma,
                         cudaFuncAttributeMaxDynamicSharedMemorySize, SMEM_BYTES);
    rnn_hmma<<<GRIDN, NTH, SMEM_BYTES>>>(
        x, W_ih0, W_hh0, b_ih0, b_hh0,
        W_ih1, W_hh1, b_ih1, b_hh1, W_fc, b_fc, out);
}

// round 6
// speedup vs baseline: 2.4331x; 1.7704x over previous
#include <cuda_runtime.h>
#include <cuda_bf16.h>
#include <cstddef>

#define BATCH 256
#define SEQ   512
#define DIN   64
#define HID   512
#define GRIDN 128
#define NTH   256

#define TM 64
#define TN 64
#define KA_PER 144          // 576 / 4
#define KB_PER 256          // 1024 / 4

#define STRIDE 264          // smem row stride (bf16 elems)
#define TILE_ELEMS (64 * STRIDE)
#define OFF_WA_HI 0
#define OFF_WA_LO (1 * TILE_ELEMS)
#define OFF_WB_HI (2 * TILE_ELEMS)
#define OFF_WB_LO (3 * TILE_ELEMS)
#define OFF_A_HI  (4 * TILE_ELEMS)
#define OFF_A_LO  (5 * TILE_ELEMS)
#define SCR_STRIDE 66       // fp32 scratch row stride
#define SMEM_BYTES (6 * TILE_ELEMS * 2 + 64 * SCR_STRIDE * 4)   // 219,648 B

typedef unsigned long long ull;

// ---------------- cross-CTA state (static scratch; allocation-free) ----------------
__device__ __nv_bfloat16 g_Xhi[BATCH * SEQ * DIN];
__device__ __nv_bfloat16 g_Xlo[BATCH * SEQ * DIN];
__device__ __nv_bfloat16 g_H1hi[2][BATCH * HID], g_H1lo[2][BATCH * HID];
__device__ __nv_bfloat16 g_H2hi[2][BATCH * HID], g_H2lo[2][BATCH * HID];
__device__ float g_PA[4ull * BATCH * HID];
__device__ float g_PB[4ull * BATCH * HID];

struct __align__(128) Line { unsigned v; unsigned pad[31]; };
__device__ Line g_leaf[8];
__device__ Line g_root;
__device__ Line g_gen;

__device__ __forceinline__ void grid_sync(int leaf) {
    __syncthreads();
    if (threadIdx.x == 0) {
        unsigned gen = *(volatile unsigned*)&g_gen.v;
        __threadfence();
        if (atomicAdd(&g_leaf[leaf].v, 1u) == 15u) {
            g_leaf[leaf].v = 0u;
            __threadfence();
            if (atomicAdd(&g_root.v, 1u) == 7u) {
                g_root.v = 0u;
                __threadfence();
                *(volatile unsigned*)&g_gen.v = gen + 1u;
            } else {
                while (*(volatile unsigned*)&g_gen.v == gen) __nanosleep(16);
            }
        } else {
            while (*(volatile unsigned*)&g_gen.v == gen) __nanosleep(16);
        }
        __threadfence();
    }
    __syncthreads();
}

__device__ __forceinline__ void mma16816(float* c, const unsigned* a, const unsigned* b) {
    asm volatile(
        "mma.sync.aligned.m16n8k16.row.col.f32.bf16.bf16.f32 "
        "{%0,%1,%2,%3}, {%4,%5,%6,%7}, {%8,%9}, {%0,%1,%2,%3};"
        : "+f"(c[0]), "+f"(c[1]), "+f"(c[2]), "+f"(c[3])
        : "r"(a[0]), "r"(a[1]), "r"(a[2]), "r"(a[3]), "r"(b[0]), "r"(b[1]));
}

__device__ __forceinline__ void split_bf16(float v, __nv_bfloat16& hi, __nv_bfloat16& lo) {
    hi = __float2bfloat16_rn(v);
    lo = __float2bfloat16_rn(v - __bfloat162float(hi));
}

__global__ void __launch_bounds__(NTH, 1) rnn_hmma(
    const float* __restrict__ x,
    const float* __restrict__ W_ih0, const float* __restrict__ W_hh0,
    const float* __restrict__ b_ih0, const float* __restrict__ b_hh0,
    const float* __restrict__ W_ih1, const float* __restrict__ W_hh1,
    const float* __restrict__ b_ih1, const float* __restrict__ b_hh1,
    const float* __restrict__ W_fc,  const float* __restrict__ b_fc,
    float* __restrict__ out)
{
    const int tid  = threadIdx.x;
    const int bid  = blockIdx.x;
    const int leaf = bid & 7;
    const int ks   = bid & 3;
    const int tile = bid >> 2;
    const int mt   = tile >> 3;
    const int nt   = tile & 7;
    const int m0   = mt * TM;
    const int n0   = nt * TN;

    extern __shared__ __nv_bfloat16 sm[];
    float* scr = (float*)(sm + 6 * TILE_ELEMS);   // 64 x 66 fp32 scratch

    // ---------- one-time: split weight slices -> SMEM ----------
    {
        const int kb = ks * KA_PER;
        for (int idx = tid; idx < 64 * KA_PER; idx += NTH) {
            int n = idx / KA_PER, k = idx - n * KA_PER;
            int kg = kb + k;
            float v = (kg < DIN) ? W_ih0[(n0 + n) * DIN + kg]
                                 : W_hh0[(n0 + n) * HID + (kg - DIN)];
            __nv_bfloat16 hi, lo; split_bf16(v, hi, lo);
            sm[OFF_WA_HI + n * STRIDE + k] = hi;
            sm[OFF_WA_LO + n * STRIDE + k] = lo;
        }
        const int kbb = ks * KB_PER;
        for (int idx = tid; idx < 64 * KB_PER; idx += NTH) {
            int n = idx / KB_PER, k = idx - n * KB_PER;
            int kg = kbb + k;
            float v = (kg < HID) ? W_ih1[(n0 + n) * HID + kg]
                                 : W_hh1[(n0 + n) * HID + (kg - HID)];
            __nv_bfloat16 hi, lo; split_bf16(v, hi, lo);
            sm[OFF_WB_HI + n * STRIDE + k] = hi;
            sm[OFF_WB_LO + n * STRIDE + k] = lo;
        }
    }
    // ---------- one-time: pre-split x ----------
    {
        const int total = BATCH * SEQ * DIN;
        for (int i = (bid * NTH + tid) * 4; i < total; i += GRIDN * NTH * 4) {
            float4 v = *(const float4*)(x + i);
            __nv_bfloat16 h0,h1,h2,h3,l0,l1,l2,l3;
            split_bf16(v.x,h0,l0); split_bf16(v.y,h1,l1);
            split_bf16(v.z,h2,l2); split_bf16(v.w,h3,l3);
            *(__nv_bfloat162*)(g_Xhi + i)     = __halves2bfloat162(h0, h1);
            *(__nv_bfloat162*)(g_Xhi + i + 2) = __halves2bfloat162(h2, h3);
            *(__nv_bfloat162*)(g_Xlo + i)     = __halves2bfloat162(l0, l1);
            *(__nv_bfloat162*)(g_Xlo + i + 2) = __halves2bfloat162(l2, l3);
        }
    }
    // ---------- zero t=-1 states (buffer 1) ----------
    {
        const int per = (BATCH * HID) / GRIDN;   // 1024
        const int base = bid * per;
        __nv_bfloat162 z = __halves2bfloat162(__float2bfloat16(0.f), __float2bfloat16(0.f));
        for (int i = tid * 2; i < per; i += NTH * 2) {
            *(__nv_bfloat162*)(&g_H1hi[1][base + i]) = z;
            *(__nv_bfloat162*)(&g_H1lo[1][base + i]) = z;
            *(__nv_bfloat162*)(&g_H2hi[1][base + i]) = z;
            *(__nv_bfloat162*)(&g_H2lo[1][base + i]) = z;
        }
    }
    grid_sync(leaf);

    // ---------- roles ----------
    const int lane = tid & 31;
    const int wid  = tid >> 5;
    const int wm   = wid & 1;
    const int wn   = (wid >> 1) & 1;
    const int wk   = wid >> 2;
    const int q    = lane >> 2;
    const int tg2  = (lane & 3) * 2;

    // staging roles (coalesced: warp spans one row's k-range)
    const int s_k   = (tid & 31) * 8;   // bf16 elem offset within k-slice
    const int s_row = tid >> 5;         // row base (0..7), step 8

    // reduce role
    const int ro = (bid << 10) + (tid << 2);
    const int rb = ro >> 9;
    const int rn = ro & (HID - 1);
    float4 biasA, biasB;
    {
        float4 bi = *(const float4*)(b_ih0 + rn);
        float4 bh = *(const float4*)(b_hh0 + rn);
        biasA = make_float4(bi.x+bh.x, bi.y+bh.y, bi.z+bh.z, bi.w+bh.w);
        bi = *(const float4*)(b_ih1 + rn);
        bh = *(const float4*)(b_hh1 + rn);
        biasB = make_float4(bi.x+bh.x, bi.y+bh.y, bi.z+bh.z, bi.w+bh.w);
    }

    // ---------- staging (fully coalesced 16B per thread, consecutive in k) ----------
    auto stageA = [&](int t, const __nv_bfloat16* h1phi, const __nv_bfloat16* h1plo) {
        if (s_k < KA_PER) {
            const int kg = ks * KA_PER + s_k;
            #pragma unroll
            for (int it = 0; it < 8; ++it) {
                int row = s_row + it * 8;
                int mgr = m0 + row;
                uint4 vh, vl;
                if (kg < DIN) {
                    size_t off = (size_t)mgr * (SEQ * DIN) + (size_t)t * DIN + kg;
                    vh = __ldcg((const uint4*)(g_Xhi + off));
                    vl = __ldcg((const uint4*)(g_Xlo + off));
                } else {
                    size_t off = (size_t)mgr * HID + (kg - DIN);
                    vh = __ldcg((const uint4*)(h1phi + off));
                    vl = __ldcg((const uint4*)(h1plo + off));
                }
                *(uint4*)(sm + OFF_A_HI + row * STRIDE + s_k) = vh;
                *(uint4*)(sm + OFF_A_LO + row * STRIDE + s_k) = vl;
            }
        }
    };
    auto stageB = [&](const __nv_bfloat16* h1phi, const __nv_bfloat16* h1plo,
                      const __nv_bfloat16* h2phi, const __nv_bfloat16* h2plo) {
        const int kg = ks * KB_PER + s_k;
        const int koff = (ks < 2) ? kg : kg - HID;
        const __nv_bfloat16* shi = (ks < 2) ? h1phi : h2phi;
        const __nv_bfloat16* slo = (ks < 2) ? h1plo : h2plo;
        #pragma unroll
        for (int it = 0; it < 8; ++it) {
            int row = s_row + it * 8;
            size_t off = (size_t)(m0 + row) * HID + koff;
            uint4 vh = __ldcg((const uint4*)(shi + off));
            uint4 vl = __ldcg((const uint4*)(slo + off));
            *(uint4*)(sm + OFF_A_HI + row * STRIDE + s_k) = vh;
            *(uint4*)(sm + OFF_A_LO + row * STRIDE + s_k) = vl;
        }
    };

    // ---------- GEMM phase: 3-split HMMA, k-halves merged in SMEM, 1 slab/CTA ----------
    auto computePhase = [&](int offWhi, int offWlo, int ks0, int ks1, float* __restrict__ Pbase) {
        float acc[2][4][4];
        #pragma unroll
        for (int f = 0; f < 2; f++)
            #pragma unroll
            for (int g = 0; g < 4; g++)
                #pragma unroll
                for (int i = 0; i < 4; i++) acc[f][g][i] = 0.f;

        const __nv_bfloat16* Ah = sm + OFF_A_HI;
        const __nv_bfloat16* Al = sm + OFF_A_LO;
        const __nv_bfloat16* Wh = sm + offWhi;
        const __nv_bfloat16* Wl = sm + offWlo;
        const int r00 = wm * 32 + q;

        for (int kst = ks0; kst < ks1; ++kst) {
            const int kb = kst * 16 + tg2;
            unsigned ah[2][4], al[2][4], bh[4][2], bl[4][2];
            #pragma unroll
            for (int f = 0; f < 2; f++) {
                int r = (r00 + f * 16) * STRIDE;
                ah[f][0] = *(const unsigned*)(Ah + r + kb);
                ah[f][1] = *(const unsigned*)(Ah + r + 8 * STRIDE + kb);
                ah[f][2] = *(const unsigned*)(Ah + r + kb + 8);
                ah[f][3] = *(const unsigned*)(Ah + r + 8 * STRIDE + kb + 8);
                al[f][0] = *(const unsigned*)(Al + r + kb);
                al[f][1] = *(const unsigned*)(Al + r + 8 * STRIDE + kb);
                al[f][2] = *(const unsigned*)(Al + r + kb + 8);
                al[f][3] = *(const unsigned*)(Al + r + 8 * STRIDE + kb + 8);
            }
            #pragma unroll
            for (int g = 0; g < 4; g++) {
                int nr = (wn * 32 + g * 8 + q) * STRIDE;
                bh[g][0] = *(const unsigned*)(Wh + nr + kb);
                bh[g][1] = *(const unsigned*)(Wh + nr + kb + 8);
                bl[g][0] = *(const unsigned*)(Wl + nr + kb);
                bl[g][1] = *(const unsigned*)(Wl + nr + kb + 8);
            }
            #pragma unroll
            for (int f = 0; f < 2; f++)
                #pragma unroll
                for (int g = 0; g < 4; g++) {
                    mma16816(acc[f][g], ah[f], bh[g]);
                    mma16816(acc[f][g], al[f], bh[g]);
                    mma16816(acc[f][g], ah[f], bl[g]);
                }
        }
        // wk=1 half -> SMEM scratch
        if (wk == 1) {
            #pragma unroll
            for (int f = 0; f < 2; f++)
                #pragma unroll
                for (int g = 0; g < 4; g++) {
                    int r = wm * 32 + f * 16 + q;
                    int c = wn * 32 + g * 8 + tg2;
                    *(float2*)(scr + r * SCR_STRIDE + c) =
                        make_float2(acc[f][g][0], acc[f][g][1]);
                    *(float2*)(scr + (r + 8) * SCR_STRIDE + c) =
                        make_float2(acc[f][g][2], acc[f][g][3]);
                }
        }
        __syncthreads();
        // wk=0 half: add scratch, store single slab (index ks)
        if (wk == 0) {
            float* P = Pbase + (size_t)ks * (BATCH * HID);
            #pragma unroll
            for (int f = 0; f < 2; f++)
                #pragma unroll
                for (int g = 0; g < 4; g++) {
                    int r = wm * 32 + f * 16 + q;
                    int c = wn * 32 + g * 8 + tg2;
                    float2 o0 = *(const float2*)(scr + r * SCR_STRIDE + c);
                    float2 o1 = *(const float2*)(scr + (r + 8) * SCR_STRIDE + c);
                    *(float2*)(P + (size_t)(m0 + r) * HID + n0 + c) =
                        make_float2(acc[f][g][0] + o0.x, acc[f][g][1] + o0.y);
                    *(float2*)(P + (size_t)(m0 + r + 8) * HID + n0 + c) =
                        make_float2(acc[f][g][2] + o1.x, acc[f][g][3] + o1.y);
                }
        }
    };

    // ---------- reduce 4 slabs + tanh + split-store ----------
    auto reduce4 = [&](const float* __restrict__ Pbase, const float4& bias,
                       __nv_bfloat16* __restrict__ dhi, __nv_bfloat16* __restrict__ dlo) {
        const float* Pb = Pbase + (size_t)rb * HID + rn;
        float4 s = bias;
        #pragma unroll
        for (int sl = 0; sl < 4; sl++) {
            float4 p = __ldcg((const float4*)(Pb + (size_t)sl * BATCH * HID));
            s.x += p.x; s.y += p.y; s.z += p.z; s.w += p.w;
        }
        float h0 = tanhf(s.x), h1 = tanhf(s.y), h2 = tanhf(s.z), h3 = tanhf(s.w);
        __nv_bfloat16 hi0,hi1,hi2,hi3, lo0,lo1,lo2,lo3;
        split_bf16(h0,hi0,lo0); split_bf16(h1,hi1,lo1);
        split_bf16(h2,hi2,lo2); split_bf16(h3,hi3,lo3);
        __nv_bfloat162 ph0 = __halves2bfloat162(hi0, hi1), ph1 = __halves2bfloat162(hi2, hi3);
        __nv_bfloat162 pl0 = __halves2bfloat162(lo0, lo1), pl1 = __halves2bfloat162(lo2, lo3);
        uint2 uh, ul2;
        uh.x = *(unsigned*)&ph0; uh.y = *(unsigned*)&ph1;
        ul2.x = *(unsigned*)&pl0; ul2.y = *(unsigned*)&pl1;
        __stcg((uint2*)(dhi + (size_t)rb * HID + rn), uh);
        __stcg((uint2*)(dlo + (size_t)rb * HID + rn), ul2);
    };

    const int ksA0 = wk ? 5 : 0, ksA1 = wk ? 9 : 5;
    const int ksB0 = wk ? 8 : 0, ksB1 = wk ? 16 : 8;

    // ============================ main pipelined loop ============================
    for (int t = 0; t < SEQ; ++t) {
        const int pp = (t + 1) & 1, pc = t & 1;
        const __nv_bfloat16* h1phi = g_H1hi[pp]; const __nv_bfloat16* h1plo = g_H1lo[pp];
        const __nv_bfloat16* h2phi = g_H2hi[pc]; const __nv_bfloat16* h2plo = g_H2lo[pc];

        stageA(t, h1phi, h1plo);
        __syncthreads();
        computePhase(OFF_WA_HI, OFF_WA_LO, ksA0, ksA1, g_PA);   // internal sync
        if (t > 0) {
            stageB(h1phi, h1plo, h2phi, h2plo);
            __syncthreads();
            computePhase(OFF_WB_HI, OFF_WB_LO, ksB0, ksB1, g_PB);
        }
        grid_sync(leaf);

        reduce4(g_PA, biasA, g_H1hi[pc], g_H1lo[pc]);
        if (t > 0) reduce4(g_PB, biasB, g_H2hi[pp], g_H2lo[pp]);
        grid_sync(leaf);
    }
    // epilogue: B(511): h1(511) in buf1, h2(510) in buf0 -> h2(511) in buf1
    stageB(g_H1hi[1], g_H1lo[1], g_H2hi[0], g_H2lo[0]);
    __syncthreads();
    computePhase(OFF_WB_HI, OFF_WB_LO, ksB0, ksB1, g_PB);
    grid_sync(leaf);
    reduce4(g_PB, biasB, g_H2hi[1], g_H2lo[1]);
    grid_sync(leaf);

    // ============================ final FC ============================
    static __shared__ float red[8];
    for (int r = 0; r < 2; ++r) {
        int b = bid * 2 + r;
        float s = 0.f;
        for (int h = tid * 2; h < HID; h += NTH * 2) {
            unsigned uh = __ldcg((const unsigned*)(&g_H2hi[1][(size_t)b * HID + h]));
            unsigned ul2 = __ldcg((const unsigned*)(&g_H2lo[1][(size_t)b * HID + h]));
            __nv_bfloat162 vh = *(__nv_bfloat162*)&uh;
            __nv_bfloat162 vl = *(__nv_bfloat162*)&ul2;
            float v0 = __bfloat162float(__low2bfloat16(vh)) + __bfloat162float(__low2bfloat16(vl));
            float v1 = __bfloat162float(__high2bfloat16(vh)) + __bfloat162float(__high2bfloat16(vl));
            s += v0 * W_fc[h] + v1 * W_fc[h + 1];
        }
        #pragma unroll
        for (int off = 16; off; off >>= 1)
            s += __shfl_down_sync(0xffffffffu, s, off);
        if ((tid & 31) == 0) red[tid >> 5] = s;
        __syncthreads();
        if (tid == 0) {
            float tot = b_fc[0];
            #pragma unroll
            for (int w = 0; w < 8; w++) tot += red[w];
            out[b] = tot;
        }
        __syncthreads();
    }
}

extern "C" void kernel_launch(void* const* d_in, const int* in_sizes, int n_in,
                              void* d_out, int out_size) {
    (void)in_sizes; (void)n_in; (void)out_size;
    const float* x     = (const float*)d_in[0];
    const float* W_ih0 = (const float*)d_in[1];
    const float* W_hh0 = (const float*)d_in[2];
    const float* b_ih0 = (const float*)d_in[3];
    const float* b_hh0 = (const float*)d_in[4];
    const float* W_ih1 = (const float*)d_in[5];
    const float* W_hh1 = (const float*)d_in[6];
    const float* b_ih1 = (const float*)d_in[7];
    const float* b_hh1 = (const float*)d_in[8];
    const float* W_fc  = (const float*)d_in[9];
    const float* b_fc  = (const float*)d_in[10];
    float* out = (float*)d_out;

    cudaFuncSetAttribute(rnn_hmma,
                         cudaFuncAttributeMaxDynamicSharedMemorySize, SMEM_BYTES);
    rnn_hmma<<<GRIDN, NTH, SMEM_BYTES>>>(
        x, W_ih0, W_hh0, b_ih0, b_hh0,
        W_ih1, W_hh1, b_ih1, b_hh1, W_fc, b_fc, out);
}

// round 7
// speedup vs baseline: 2.6021x; 1.0695x over previous
#include <cuda_runtime.h>
#include <cuda_bf16.h>
#include <cstddef>

#define BATCH 256
#define SEQ   512
#define DIN   64
#define HID   512
#define GRIDN 128
#define NTH   256

#define TM 64
#define TN 64
#define KA_PER 144          // 576 / 4
#define KB_PER 256          // 1024 / 4

#define SA 152              // A-phase row stride (bf16 elems): 16B-aligned, conflict-free
#define SB 264              // B-phase row stride

// SMEM element offsets (bf16)
#define OFF_WA_HI 0
#define OFF_WA_LO (OFF_WA_HI + 64 * SA)
#define OFF_AA_HI (OFF_WA_LO + 64 * SA)
#define OFF_AA_LO (OFF_AA_HI + 64 * SA)
#define OFF_WB_HI (OFF_AA_LO + 64 * SA)
#define OFF_WB_LO (OFF_WB_HI + 64 * SB)
#define OFF_AB_HI (OFF_WB_LO + 64 * SB)
#define OFF_AB_LO (OFF_AB_HI + 64 * SB)
#define ELEMS_TOT (OFF_AB_LO + 64 * SB)          // 106,496 bf16
#define SCR_STRIDE 66
#define SMEM_BYTES (ELEMS_TOT * 2 + 64 * SCR_STRIDE * 4)   // 229,888 B

typedef unsigned long long ull;

// ---------------- cross-CTA state (static scratch; allocation-free) ----------------
__device__ __nv_bfloat16 g_Xhi[BATCH * SEQ * DIN];
__device__ __nv_bfloat16 g_Xlo[BATCH * SEQ * DIN];
__device__ __nv_bfloat16 g_H1hi[2][BATCH * HID], g_H1lo[2][BATCH * HID];
__device__ __nv_bfloat16 g_H2hi[2][BATCH * HID], g_H2lo[2][BATCH * HID];
__device__ float g_PA[4ull * BATCH * HID];
__device__ float g_PB[4ull * BATCH * HID];

struct __align__(128) Line { unsigned v; unsigned pad[31]; };
__device__ Line g_leaf[8];
__device__ Line g_root;
__device__ Line g_gen;

__device__ __forceinline__ void grid_sync(int leaf) {
    __syncthreads();
    if (threadIdx.x == 0) {
        unsigned gen = *(volatile unsigned*)&g_gen.v;
        __threadfence();
        if (atomicAdd(&g_leaf[leaf].v, 1u) == 15u) {
            g_leaf[leaf].v = 0u;
            __threadfence();
            if (atomicAdd(&g_root.v, 1u) == 7u) {
                g_root.v = 0u;
                __threadfence();
                *(volatile unsigned*)&g_gen.v = gen + 1u;
            } else {
                while (*(volatile unsigned*)&g_gen.v == gen) __nanosleep(16);
            }
        } else {
            while (*(volatile unsigned*)&g_gen.v == gen) __nanosleep(16);
        }
        __threadfence();
    }
    __syncthreads();
}

__device__ __forceinline__ void mma16816(float* c, const unsigned* a, const unsigned* b) {
    asm volatile(
        "mma.sync.aligned.m16n8k16.row.col.f32.bf16.bf16.f32 "
        "{%0,%1,%2,%3}, {%4,%5,%6,%7}, {%8,%9}, {%0,%1,%2,%3};"
        : "+f"(c[0]), "+f"(c[1]), "+f"(c[2]), "+f"(c[3])
        : "r"(a[0]), "r"(a[1]), "r"(a[2]), "r"(a[3]), "r"(b[0]), "r"(b[1]));
}

#define CP16(dst_u32, src_ptr) \
    asm volatile("cp.async.cg.shared.global [%0], [%1], 16;" \
                 :: "r"(dst_u32), "l"(src_ptr))
#define CP_COMMIT() asm volatile("cp.async.commit_group;")
#define CP_WAIT(n)  asm volatile("cp.async.wait_group %0;" :: "n"(n))

__device__ __forceinline__ void split_bf16(float v, __nv_bfloat16& hi, __nv_bfloat16& lo) {
    hi = __float2bfloat16_rn(v);
    lo = __float2bfloat16_rn(v - __bfloat162float(hi));
}

__global__ void __launch_bounds__(NTH, 1) rnn_hmma(
    const float* __restrict__ x,
    const float* __restrict__ W_ih0, const float* __restrict__ W_hh0,
    const float* __restrict__ b_ih0, const float* __restrict__ b_hh0,
    const float* __restrict__ W_ih1, const float* __restrict__ W_hh1,
    const float* __restrict__ b_ih1, const float* __restrict__ b_hh1,
    const float* __restrict__ W_fc,  const float* __restrict__ b_fc,
    float* __restrict__ out)
{
    const int tid  = threadIdx.x;
    const int bid  = blockIdx.x;
    const int leaf = bid & 7;
    const int ks   = bid & 3;
    const int tile = bid >> 2;
    const int mt   = tile >> 3;
    const int nt   = tile & 7;
    const int m0   = mt * TM;
    const int n0   = nt * TN;

    extern __shared__ __nv_bfloat16 sm[];
    float* scr = (float*)(sm + ELEMS_TOT);
    const unsigned sm_u32 = (unsigned)__cvta_generic_to_shared(sm);

    // ---------- one-time: split weight slices -> SMEM ----------
    {
        const int kb = ks * KA_PER;
        for (int idx = tid; idx < 64 * KA_PER; idx += NTH) {
            int n = idx / KA_PER, k = idx - n * KA_PER;
            int kg = kb + k;
            float v = (kg < DIN) ? W_ih0[(n0 + n) * DIN + kg]
                                 : W_hh0[(n0 + n) * HID + (kg - DIN)];
            __nv_bfloat16 hi, lo; split_bf16(v, hi, lo);
            sm[OFF_WA_HI + n * SA + k] = hi;
            sm[OFF_WA_LO + n * SA + k] = lo;
        }
        const int kbb = ks * KB_PER;
        for (int idx = tid; idx < 64 * KB_PER; idx += NTH) {
            int n = idx / KB_PER, k = idx - n * KB_PER;
            int kg = kbb + k;
            float v = (kg < HID) ? W_ih1[(n0 + n) * HID + kg]
                                 : W_hh1[(n0 + n) * HID + (kg - HID)];
            __nv_bfloat16 hi, lo; split_bf16(v, hi, lo);
            sm[OFF_WB_HI + n * SB + k] = hi;
            sm[OFF_WB_LO + n * SB + k] = lo;
        }
    }
    // ---------- one-time: pre-split x ----------
    {
        const int total = BATCH * SEQ * DIN;
        for (int i = (bid * NTH + tid) * 4; i < total; i += GRIDN * NTH * 4) {
            float4 v = *(const float4*)(x + i);
            __nv_bfloat16 h0,h1,h2,h3,l0,l1,l2,l3;
            split_bf16(v.x,h0,l0); split_bf16(v.y,h1,l1);
            split_bf16(v.z,h2,l2); split_bf16(v.w,h3,l3);
            *(__nv_bfloat162*)(g_Xhi + i)     = __halves2bfloat162(h0, h1);
            *(__nv_bfloat162*)(g_Xhi + i + 2) = __halves2bfloat162(h2, h3);
            *(__nv_bfloat162*)(g_Xlo + i)     = __halves2bfloat162(l0, l1);
            *(__nv_bfloat162*)(g_Xlo + i + 2) = __halves2bfloat162(l2, l3);
        }
    }
    // ---------- zero t=-1 states (buffer 1) ----------
    {
        const int per = (BATCH * HID) / GRIDN;
        const int base = bid * per;
        __nv_bfloat162 z = __halves2bfloat162(__float2bfloat16(0.f), __float2bfloat16(0.f));
        for (int i = tid * 2; i < per; i += NTH * 2) {
            *(__nv_bfloat162*)(&g_H1hi[1][base + i]) = z;
            *(__nv_bfloat162*)(&g_H1lo[1][base + i]) = z;
            *(__nv_bfloat162*)(&g_H2hi[1][base + i]) = z;
            *(__nv_bfloat162*)(&g_H2lo[1][base + i]) = z;
        }
    }
    grid_sync(leaf);

    // ---------- roles ----------
    const int lane = tid & 31;
    const int wid  = tid >> 5;
    const int wm   = wid & 1;
    const int wn   = (wid >> 1) & 1;
    const int wk   = wid >> 2;
    const int q    = lane >> 2;
    const int tg2  = (lane & 3) * 2;

    const int s_k   = lane * 8;       // bf16 k-offset (16B per thread)
    const int s_row = wid;            // row base, step 8

    // reduce role
    const int ro = (bid << 10) + (tid << 2);
    const int rb = ro >> 9;
    const int rn = ro & (HID - 1);
    float4 biasA, biasB;
    {
        float4 bi = *(const float4*)(b_ih0 + rn);
        float4 bh = *(const float4*)(b_hh0 + rn);
        biasA = make_float4(bi.x+bh.x, bi.y+bh.y, bi.z+bh.z, bi.w+bh.w);
        bi = *(const float4*)(b_ih1 + rn);
        bh = *(const float4*)(b_hh1 + rn);
        biasB = make_float4(bi.x+bh.x, bi.y+bh.y, bi.z+bh.z, bi.w+bh.w);
    }

    // ---------- async staging ----------
    auto stageA_async = [&](int t, const __nv_bfloat16* h1phi, const __nv_bfloat16* h1plo) {
        if (s_k < KA_PER) {
            const int kg = ks * KA_PER + s_k;
            #pragma unroll
            for (int it = 0; it < 8; ++it) {
                int row = s_row + it * 8;
                int mgr = m0 + row;
                const __nv_bfloat16 *ph, *pl;
                if (kg < DIN) {
                    size_t off = (size_t)mgr * (SEQ * DIN) + (size_t)t * DIN + kg;
                    ph = g_Xhi + off; pl = g_Xlo + off;
                } else {
                    size_t off = (size_t)mgr * HID + (kg - DIN);
                    ph = h1phi + off; pl = h1plo + off;
                }
                CP16(sm_u32 + (OFF_AA_HI + row * SA + s_k) * 2, ph);
                CP16(sm_u32 + (OFF_AA_LO + row * SA + s_k) * 2, pl);
            }
        }
        CP_COMMIT();
    };
    auto stageB_async = [&](const __nv_bfloat16* h1phi, const __nv_bfloat16* h1plo,
                            const __nv_bfloat16* h2phi, const __nv_bfloat16* h2plo) {
        const int kg = ks * KB_PER + s_k;
        const int koff = (ks < 2) ? kg : kg - HID;
        const __nv_bfloat16* shi = (ks < 2) ? h1phi : h2phi;
        const __nv_bfloat16* slo = (ks < 2) ? h1plo : h2plo;
        #pragma unroll
        for (int it = 0; it < 8; ++it) {
            int row = s_row + it * 8;
            size_t off = (size_t)(m0 + row) * HID + koff;
            CP16(sm_u32 + (OFF_AB_HI + row * SB + s_k) * 2, shi + off);
            CP16(sm_u32 + (OFF_AB_LO + row * SB + s_k) * 2, slo + off);
        }
        CP_COMMIT();
    };

    // ---------- GEMM phase (3-split HMMA, k-halves merged via SMEM, 1 slab) ----------
    auto computePhase = [&](int offWhi, int offWlo, int offAhi, int offAlo, int st,
                            int ks0, int ks1, float* __restrict__ Pbase) {
        float acc[2][4][4];
        #pragma unroll
        for (int f = 0; f < 2; f++)
            #pragma unroll
            for (int g = 0; g < 4; g++)
                #pragma unroll
                for (int i = 0; i < 4; i++) acc[f][g][i] = 0.f;

        const __nv_bfloat16* Ah = sm + offAhi;
        const __nv_bfloat16* Al = sm + offAlo;
        const __nv_bfloat16* Wh = sm + offWhi;
        const __nv_bfloat16* Wl = sm + offWlo;
        const int r00 = wm * 32 + q;

        for (int kst = ks0; kst < ks1; ++kst) {
            const int kb = kst * 16 + tg2;
            unsigned ah[2][4], al[2][4], bh[4][2], bl[4][2];
            #pragma unroll
            for (int f = 0; f < 2; f++) {
                int r = (r00 + f * 16) * st;
                ah[f][0] = *(const unsigned*)(Ah + r + kb);
                ah[f][1] = *(const unsigned*)(Ah + r + 8 * st + kb);
                ah[f][2] = *(const unsigned*)(Ah + r + kb + 8);
                ah[f][3] = *(const unsigned*)(Ah + r + 8 * st + kb + 8);
                al[f][0] = *(const unsigned*)(Al + r + kb);
                al[f][1] = *(const unsigned*)(Al + r + 8 * st + kb);
                al[f][2] = *(const unsigned*)(Al + r + kb + 8);
                al[f][3] = *(const unsigned*)(Al + r + 8 * st + kb + 8);
            }
            #pragma unroll
            for (int g = 0; g < 4; g++) {
                int nr = (wn * 32 + g * 8 + q) * st;
                bh[g][0] = *(const unsigned*)(Wh + nr + kb);
                bh[g][1] = *(const unsigned*)(Wh + nr + kb + 8);
                bl[g][0] = *(const unsigned*)(Wl + nr + kb);
                bl[g][1] = *(const unsigned*)(Wl + nr + kb + 8);
            }
            #pragma unroll
            for (int f = 0; f < 2; f++)
                #pragma unroll
                for (int g = 0; g < 4; g++) {
                    mma16816(acc[f][g], ah[f], bh[g]);
                    mma16816(acc[f][g], al[f], bh[g]);
                    mma16816(acc[f][g], ah[f], bl[g]);
                }
        }
        if (wk == 1) {
            #pragma unroll
            for (int f = 0; f < 2; f++)
                #pragma unroll
                for (int g = 0; g < 4; g++) {
                    int r = wm * 32 + f * 16 + q;
                    int c = wn * 32 + g * 8 + tg2;
                    *(float2*)(scr + r * SCR_STRIDE + c) =
                        make_float2(acc[f][g][0], acc[f][g][1]);
                    *(float2*)(scr + (r + 8) * SCR_STRIDE + c) =
                        make_float2(acc[f][g][2], acc[f][g][3]);
                }
        }
        __syncthreads();
        if (wk == 0) {
            float* P = Pbase + (size_t)ks * (BATCH * HID);
            #pragma unroll
            for (int f = 0; f < 2; f++)
                #pragma unroll
                for (int g = 0; g < 4; g++) {
                    int r = wm * 32 + f * 16 + q;
                    int c = wn * 32 + g * 8 + tg2;
                    float2 o0 = *(const float2*)(scr + r * SCR_STRIDE + c);
                    float2 o1 = *(const float2*)(scr + (r + 8) * SCR_STRIDE + c);
                    *(float2*)(P + (size_t)(m0 + r) * HID + n0 + c) =
                        make_float2(acc[f][g][0] + o0.x, acc[f][g][1] + o0.y);
                    *(float2*)(P + (size_t)(m0 + r + 8) * HID + n0 + c) =
                        make_float2(acc[f][g][2] + o1.x, acc[f][g][3] + o1.y);
                }
        }
    };

    // ---------- merged reduce: loads first (MLP 8), then tanh + split-store ----------
    auto reduceAB = [&](bool doB, __nv_bfloat16* d1hi, __nv_bfloat16* d1lo,
                        __nv_bfloat16* d2hi, __nv_bfloat16* d2lo) {
        float4 pa[4], pb[4];
        const float* PbA = g_PA + (size_t)rb * HID + rn;
        const float* PbB = g_PB + (size_t)rb * HID + rn;
        #pragma unroll
        for (int sl = 0; sl < 4; sl++)
            pa[sl] = __ldcg((const float4*)(PbA + (size_t)sl * BATCH * HID));
        if (doB) {
            #pragma unroll
            for (int sl = 0; sl < 4; sl++)
                pb[sl] = __ldcg((const float4*)(PbB + (size_t)sl * BATCH * HID));
        }
        {
            float4 s = biasA;
            #pragma unroll
            for (int sl = 0; sl < 4; sl++) {
                s.x += pa[sl].x; s.y += pa[sl].y; s.z += pa[sl].z; s.w += pa[sl].w;
            }
            float h0 = tanhf(s.x), h1 = tanhf(s.y), h2 = tanhf(s.z), h3 = tanhf(s.w);
            __nv_bfloat16 hi0,hi1,hi2,hi3, lo0,lo1,lo2,lo3;
            split_bf16(h0,hi0,lo0); split_bf16(h1,hi1,lo1);
            split_bf16(h2,hi2,lo2); split_bf16(h3,hi3,lo3);
            __nv_bfloat162 ph0 = __halves2bfloat162(hi0,hi1), ph1 = __halves2bfloat162(hi2,hi3);
            __nv_bfloat162 pl0 = __halves2bfloat162(lo0,lo1), pl1 = __halves2bfloat162(lo2,lo3);
            uint2 uh, ul;
            uh.x = *(unsigned*)&ph0; uh.y = *(unsigned*)&ph1;
            ul.x = *(unsigned*)&pl0; ul.y = *(unsigned*)&pl1;
            __stcg((uint2*)(d1hi + (size_t)rb * HID + rn), uh);
            __stcg((uint2*)(d1lo + (size_t)rb * HID + rn), ul);
        }
        if (doB) {
            float4 s = biasB;
            #pragma unroll
            for (int sl = 0; sl < 4; sl++) {
                s.x += pb[sl].x; s.y += pb[sl].y; s.z += pb[sl].z; s.w += pb[sl].w;
            }
            float h0 = tanhf(s.x), h1 = tanhf(s.y), h2 = tanhf(s.z), h3 = tanhf(s.w);
            __nv_bfloat16 hi0,hi1,hi2,hi3, lo0,lo1,lo2,lo3;
            split_bf16(h0,hi0,lo0); split_bf16(h1,hi1,lo1);
            split_bf16(h2,hi2,lo2); split_bf16(h3,hi3,lo3);
            __nv_bfloat162 ph0 = __halves2bfloat162(hi0,hi1), ph1 = __halves2bfloat162(hi2,hi3);
            __nv_bfloat162 pl0 = __halves2bfloat162(lo0,lo1), pl1 = __halves2bfloat162(lo2,lo3);
            uint2 uh, ul;
            uh.x = *(unsigned*)&ph0; uh.y = *(unsigned*)&ph1;
            ul.x = *(unsigned*)&pl0; ul.y = *(unsigned*)&pl1;
            __stcg((uint2*)(d2hi + (size_t)rb * HID + rn), uh);
            __stcg((uint2*)(d2lo + (size_t)rb * HID + rn), ul);
        }
    };

    const int ksA0 = wk ? 5 : 0, ksA1 = wk ? 9 : 5;
    const int ksB0 = wk ? 8 : 0, ksB1 = wk ? 16 : 8;

    // ============================ main pipelined loop ============================
    for (int t = 0; t < SEQ; ++t) {
        const int pp = (t + 1) & 1, pc = t & 1;
        const __nv_bfloat16* h1phi = g_H1hi[pp]; const __nv_bfloat16* h1plo = g_H1lo[pp];
        const __nv_bfloat16* h2phi = g_H2hi[pc]; const __nv_bfloat16* h2plo = g_H2lo[pc];

        stageA_async(t, h1phi, h1plo);
        if (t > 0) {
            stageB_async(h1phi, h1plo, h2phi, h2plo);
            CP_WAIT(1);                  // A landed; B still in flight
        } else {
            CP_WAIT(0);
        }
        __syncthreads();
        computePhase(OFF_WA_HI, OFF_WA_LO, OFF_AA_HI, OFF_AA_LO, SA, ksA0, ksA1, g_PA);
        if (t > 0) {
            CP_WAIT(0);
            __syncthreads();
            computePhase(OFF_WB_HI, OFF_WB_LO, OFF_AB_HI, OFF_AB_LO, SB, ksB0, ksB1, g_PB);
        }
        grid_sync(leaf);

        reduceAB(t > 0, g_H1hi[pc], g_H1lo[pc], g_H2hi[pp], g_H2lo[pp]);
        grid_sync(leaf);
    }
    // epilogue: B(511): h1(511) in buf1, h2(510) in buf0 -> h2(511) in buf1
    stageB_async(g_H1hi[1], g_H1lo[1], g_H2hi[0], g_H2lo[0]);
    CP_WAIT(0);
    __syncthreads();
    computePhase(OFF_WB_HI, OFF_WB_LO, OFF_AB_HI, OFF_AB_LO, SB, ksB0, ksB1, g_PB);
    grid_sync(leaf);
    {
        // reduce B only into g_H2[1]
        float4 pb[4];
        const float* PbB = g_PB + (size_t)rb * HID + rn;
        #pragma unroll
        for (int sl = 0; sl < 4; sl++)
            pb[sl] = __ldcg((const float4*)(PbB + (size_t)sl * BATCH * HID));
        float4 s = biasB;
        #pragma unroll
        for (int sl = 0; sl < 4; sl++) {
            s.x += pb[sl].x; s.y += pb[sl].y; s.z += pb[sl].z; s.w += pb[sl].w;
        }
        float h0 = tanhf(s.x), h1 = tanhf(s.y), h2 = tanhf(s.z), h3 = tanhf(s.w);
        __nv_bfloat16 hi0,hi1,hi2,hi3, lo0,lo1,lo2,lo3;
        split_bf16(h0,hi0,lo0); split_bf16(h1,hi1,lo1);
        split_bf16(h2,hi2,lo2); split_bf16(h3,hi3,lo3);
        __nv_bfloat162 ph0 = __halves2bfloat162(hi0,hi1), ph1 = __halves2bfloat162(hi2,hi3);
        __nv_bfloat162 pl0 = __halves2bfloat162(lo0,lo1), pl1 = __halves2bfloat162(lo2,lo3);
        uint2 uh, ul;
        uh.x = *(unsigned*)&ph0; uh.y = *(unsigned*)&ph1;
        ul.x = *(unsigned*)&pl0; ul.y = *(unsigned*)&pl1;
        __stcg((uint2*)(g_H2hi[1] + (size_t)rb * HID + rn), uh);
        __stcg((uint2*)(g_H2lo[1] + (size_t)rb * HID + rn), ul);
    }
    grid_sync(leaf);

    // ============================ final FC ============================
    static __shared__ float red[8];
    for (int r = 0; r < 2; ++r) {
        int b = bid * 2 + r;
        float s = 0.f;
        for (int h = tid * 2; h < HID; h += NTH * 2) {
            unsigned uh = __ldcg((const unsigned*)(&g_H2hi[1][(size_t)b * HID + h]));
            unsigned ul = __ldcg((const unsigned*)(&g_H2lo[1][(size_t)b * HID + h]));
            __nv_bfloat162 vh = *(__nv_bfloat162*)&uh;
            __nv_bfloat162 vl = *(__nv_bfloat162*)&ul;
            float v0 = __bfloat162float(__low2bfloat16(vh)) + __bfloat162float(__low2bfloat16(vl));
            float v1 = __bfloat162float(__high2bfloat16(vh)) + __bfloat162float(__high2bfloat16(vl));
            s += v0 * W_fc[h] + v1 * W_fc[h + 1];
        }
        #pragma unroll
        for (int off = 16; off; off >>= 1)
            s += __shfl_down_sync(0xffffffffu, s, off);
        if ((tid & 31) == 0) red[tid >> 5] = s;
        __syncthreads();
        if (tid == 0) {
            float tot = b_fc[0];
            #pragma unroll
            for (int w = 0; w < 8; w++) tot += red[w];
            out[b] = tot;
        }
        __syncthreads();
    }
}

extern "C" void kernel_launch(void* const* d_in, const int* in_sizes, int n_in,
                              void* d_out, int out_size) {
    (void)in_sizes; (void)n_in; (void)out_size;
    const float* x     = (const float*)d_in[0];
    const float* W_ih0 = (const float*)d_in[1];
    const float* W_hh0 = (const float*)d_in[2];
    const float* b_ih0 = (const float*)d_in[3];
    const float* b_hh0 = (const float*)d_in[4];
    const float* W_ih1 = (const float*)d_in[5];
    const float* W_hh1 = (const float*)d_in[6];
    const float* b_ih1 = (const float*)d_in[7];
    const float* b_hh1 = (const float*)d_in[8];
    const float* W_fc  = (const float*)d_in[9];
    const float* b_fc  = (const float*)d_in[10];
    float* out = (float*)d_out;

    cudaFuncSetAttribute(rnn_hmma,
                         cudaFuncAttributeMaxDynamicSharedMemorySize, SMEM_BYTES);
    rnn_hmma<<<GRIDN, NTH, SMEM_BYTES>>>(
        x, W_ih0, W_hh0, b_ih0, b_hh0,
        W_ih1, W_hh1, b_ih1, b_hh1, W_fc, b_fc, out);
}

// round 8
// speedup vs baseline: 2.9780x; 1.1445x over previous
#include <cuda_runtime.h>
#include <cuda_bf16.h>
#include <cstddef>

#define BATCH 256
#define SEQ   512
#define DIN   64
#define HID   512
#define GRIDN 128
#define NTH   256

#define TM 64
#define TN 64
#define KA_PER 144          // 576 / 4
#define KB_PER 256          // 1024 / 4

#define SA 152              // A-phase row stride (bf16 elems)
#define SB 264              // B-phase row stride

#define OFF_WA_HI 0
#define OFF_WA_LO (OFF_WA_HI + 64 * SA)
#define OFF_AA_HI (OFF_WA_LO + 64 * SA)
#define OFF_AA_LO (OFF_AA_HI + 64 * SA)
#define OFF_WB_HI (OFF_AA_LO + 64 * SA)
#define OFF_WB_LO (OFF_WB_HI + 64 * SB)
#define OFF_AB_HI (OFF_WB_LO + 64 * SB)
#define OFF_AB_LO (OFF_AB_HI + 64 * SB)
#define ELEMS_TOT (OFF_AB_LO + 64 * SB)          // 106,496 bf16 = 212,992 B
#define SCR_STRIDE 68                            // fp32; 16B-aligned rows
#define SMEM_BYTES (ELEMS_TOT * 2 + 64 * SCR_STRIDE * 4)   // 230,400 B

typedef unsigned long long ull;

// ---------------- cross-CTA state (static scratch; allocation-free) ----------------
__device__ __nv_bfloat16 g_Xhi[BATCH * SEQ * DIN];
__device__ __nv_bfloat16 g_Xlo[BATCH * SEQ * DIN];
__device__ __nv_bfloat16 g_H1hi[2][BATCH * HID], g_H1lo[2][BATCH * HID];
__device__ __nv_bfloat16 g_H2hi[2][BATCH * HID], g_H2lo[2][BATCH * HID];

struct __align__(128) Line { unsigned v; unsigned pad[31]; };
__device__ Line g_leaf[8];
__device__ Line g_root;
__device__ Line g_gen;

__device__ __forceinline__ void grid_sync(int leaf) {
    __syncthreads();
    if (threadIdx.x == 0) {
        unsigned gen = *(volatile unsigned*)&g_gen.v;
        __threadfence();
        if (atomicAdd(&g_leaf[leaf].v, 1u) == 15u) {
            g_leaf[leaf].v = 0u;
            __threadfence();
            if (atomicAdd(&g_root.v, 1u) == 7u) {
                g_root.v = 0u;
                __threadfence();
                *(volatile unsigned*)&g_gen.v = gen + 1u;
            } else {
                while (*(volatile unsigned*)&g_gen.v == gen) __nanosleep(16);
            }
        } else {
            while (*(volatile unsigned*)&g_gen.v == gen) __nanosleep(16);
        }
        __threadfence();
    }
    __syncthreads();
}

#define CLUSTER_SYNC() do { \
    asm volatile("barrier.cluster.arrive.aligned;" ::: "memory"); \
    asm volatile("barrier.cluster.wait.aligned;" ::: "memory"); \
} while (0)

__device__ __forceinline__ unsigned cluster_rank() {
    unsigned r;
    asm("mov.u32 %0, %%cluster_ctarank;" : "=r"(r));
    return r;
}
__device__ __forceinline__ unsigned mapa_rank(unsigned smaddr, unsigned rank) {
    unsigned r;
    asm("mapa.shared::cluster.u32 %0, %1, %2;" : "=r"(r) : "r"(smaddr), "r"(rank));
    return r;
}
__device__ __forceinline__ float4 ld_dsmem_f4(unsigned addr) {
    float4 v;
    asm volatile("ld.shared::cluster.v4.f32 {%0,%1,%2,%3}, [%4];"
                 : "=f"(v.x), "=f"(v.y), "=f"(v.z), "=f"(v.w) : "r"(addr));
    return v;
}

__device__ __forceinline__ void mma16816(float* c, const unsigned* a, const unsigned* b) {
    asm volatile(
        "mma.sync.aligned.m16n8k16.row.col.f32.bf16.bf16.f32 "
        "{%0,%1,%2,%3}, {%4,%5,%6,%7}, {%8,%9}, {%0,%1,%2,%3};"
        : "+f"(c[0]), "+f"(c[1]), "+f"(c[2]), "+f"(c[3])
        : "r"(a[0]), "r"(a[1]), "r"(a[2]), "r"(a[3]), "r"(b[0]), "r"(b[1]));
}

#define CP16(dst_u32, src_ptr) \
    asm volatile("cp.async.cg.shared.global [%0], [%1], 16;" \
                 :: "r"(dst_u32), "l"(src_ptr))
#define CP_COMMIT() asm volatile("cp.async.commit_group;")
#define CP_WAIT(n)  asm volatile("cp.async.wait_group %0;" :: "n"(n))

__device__ __forceinline__ void split_bf16(float v, __nv_bfloat16& hi, __nv_bfloat16& lo) {
    hi = __float2bfloat16_rn(v);
    lo = __float2bfloat16_rn(v - __bfloat162float(hi));
}

__global__ void __launch_bounds__(NTH, 1) __cluster_dims__(4, 1, 1) rnn_hmma(
    const float* __restrict__ x,
    const float* __restrict__ W_ih0, const float* __restrict__ W_hh0,
    const float* __restrict__ b_ih0, const float* __restrict__ b_hh0,
    const float* __restrict__ W_ih1, const float* __restrict__ W_hh1,
    const float* __restrict__ b_ih1, const float* __restrict__ b_hh1,
    const float* __restrict__ W_fc,  const float* __restrict__ b_fc,
    float* __restrict__ out)
{
    const int tid  = threadIdx.x;
    const int bid  = blockIdx.x;
    const int leaf = bid & 7;
    const int ks   = bid & 3;        // == cluster rank
    const int tile = bid >> 2;
    const int mt   = tile >> 3;
    const int nt   = tile & 7;
    const int m0   = mt * TM;
    const int n0   = nt * TN;

    extern __shared__ __nv_bfloat16 sm[];
    float* scr = (float*)(sm + ELEMS_TOT);
    const unsigned sm_u32  = (unsigned)__cvta_generic_to_shared(sm);
    const unsigned scr_u32 = sm_u32 + ELEMS_TOT * 2;

    // ---------- one-time: split weight slices -> SMEM ----------
    {
        const int kb = ks * KA_PER;
        for (int idx = tid; idx < 64 * KA_PER; idx += NTH) {
            int n = idx / KA_PER, k = idx - n * KA_PER;
            int kg = kb + k;
            float v = (kg < DIN) ? W_ih0[(n0 + n) * DIN + kg]
                                 : W_hh0[(n0 + n) * HID + (kg - DIN)];
            __nv_bfloat16 hi, lo; split_bf16(v, hi, lo);
            sm[OFF_WA_HI + n * SA + k] = hi;
            sm[OFF_WA_LO + n * SA + k] = lo;
        }
        const int kbb = ks * KB_PER;
        for (int idx = tid; idx < 64 * KB_PER; idx += NTH) {
            int n = idx / KB_PER, k = idx - n * KB_PER;
            int kg = kbb + k;
            float v = (kg < HID) ? W_ih1[(n0 + n) * HID + kg]
                                 : W_hh1[(n0 + n) * HID + (kg - HID)];
            __nv_bfloat16 hi, lo; split_bf16(v, hi, lo);
            sm[OFF_WB_HI + n * SB + k] = hi;
            sm[OFF_WB_LO + n * SB + k] = lo;
        }
    }
    // ---------- one-time: pre-split x ----------
    {
        const int total = BATCH * SEQ * DIN;
        for (int i = (bid * NTH + tid) * 4; i < total; i += GRIDN * NTH * 4) {
            float4 v = *(const float4*)(x + i);
            __nv_bfloat16 h0,h1,h2,h3,l0,l1,l2,l3;
            split_bf16(v.x,h0,l0); split_bf16(v.y,h1,l1);
            split_bf16(v.z,h2,l2); split_bf16(v.w,h3,l3);
            *(__nv_bfloat162*)(g_Xhi + i)     = __halves2bfloat162(h0, h1);
            *(__nv_bfloat162*)(g_Xhi + i + 2) = __halves2bfloat162(h2, h3);
            *(__nv_bfloat162*)(g_Xlo + i)     = __halves2bfloat162(l0, l1);
            *(__nv_bfloat162*)(g_Xlo + i + 2) = __halves2bfloat162(l2, l3);
        }
    }
    // ---------- zero t=-1 states (buffer 1) ----------
    {
        const int per = (BATCH * HID) / GRIDN;
        const int base = bid * per;
        __nv_bfloat162 z = __halves2bfloat162(__float2bfloat16(0.f), __float2bfloat16(0.f));
        for (int i = tid * 2; i < per; i += NTH * 2) {
            *(__nv_bfloat162*)(&g_H1hi[1][base + i]) = z;
            *(__nv_bfloat162*)(&g_H1lo[1][base + i]) = z;
            *(__nv_bfloat162*)(&g_H2hi[1][base + i]) = z;
            *(__nv_bfloat162*)(&g_H2lo[1][base + i]) = z;
        }
    }
    grid_sync(leaf);

    // ---------- roles ----------
    const int lane = tid & 31;
    const int wid  = tid >> 5;
    const int wm   = wid & 1;
    const int wn   = (wid >> 1) & 1;
    const int wk   = wid >> 2;
    const int q    = lane >> 2;
    const int tg2  = (lane & 3) * 2;

    const int s_k   = lane * 8;
    const int s_row = wid;

    // reduce role: cluster-wide 1024 threads cover 64x64 tile, 4 cols each
    const unsigned crank = cluster_rank();      // == ks
    const int gtid = (int)crank * NTH + tid;
    const int rr = gtid >> 4;                   // 0..63  (m within tile)
    const int cc = (gtid & 15) << 2;            // 0..60  (n within tile)
    float4 biasA, biasB;
    {
        float4 bi = *(const float4*)(b_ih0 + n0 + cc);
        float4 bh = *(const float4*)(b_hh0 + n0 + cc);
        biasA = make_float4(bi.x+bh.x, bi.y+bh.y, bi.z+bh.z, bi.w+bh.w);
        bi = *(const float4*)(b_ih1 + n0 + cc);
        bh = *(const float4*)(b_hh1 + n0 + cc);
        biasB = make_float4(bi.x+bh.x, bi.y+bh.y, bi.z+bh.z, bi.w+bh.w);
    }
    const unsigned scr_off = scr_u32 + (unsigned)(rr * SCR_STRIDE + cc) * 4u;

    // ---------- async staging ----------
    auto stageA_async = [&](int t, const __nv_bfloat16* h1phi, const __nv_bfloat16* h1plo) {
        if (s_k < KA_PER) {
            const int kg = ks * KA_PER + s_k;
            #pragma unroll
            for (int it = 0; it < 8; ++it) {
                int row = s_row + it * 8;
                int mgr = m0 + row;
                const __nv_bfloat16 *ph, *pl;
                if (kg < DIN) {
                    size_t off = (size_t)mgr * (SEQ * DIN) + (size_t)t * DIN + kg;
                    ph = g_Xhi + off; pl = g_Xlo + off;
                } else {
                    size_t off = (size_t)mgr * HID + (kg - DIN);
                    ph = h1phi + off; pl = h1plo + off;
                }
                CP16(sm_u32 + (OFF_AA_HI + row * SA + s_k) * 2, ph);
                CP16(sm_u32 + (OFF_AA_LO + row * SA + s_k) * 2, pl);
            }
        }
        CP_COMMIT();
    };
    auto stageB_async = [&](const __nv_bfloat16* h1phi, const __nv_bfloat16* h1plo,
                            const __nv_bfloat16* h2phi, const __nv_bfloat16* h2plo) {
        const int kg = ks * KB_PER + s_k;
        const int koff = (ks < 2) ? kg : kg - HID;
        const __nv_bfloat16* shi = (ks < 2) ? h1phi : h2phi;
        const __nv_bfloat16* slo = (ks < 2) ? h1plo : h2plo;
        #pragma unroll
        for (int it = 0; it < 8; ++it) {
            int row = s_row + it * 8;
            size_t off = (size_t)(m0 + row) * HID + koff;
            CP16(sm_u32 + (OFF_AB_HI + row * SB + s_k) * 2, shi + off);
            CP16(sm_u32 + (OFF_AB_LO + row * SB + s_k) * 2, slo + off);
        }
        CP_COMMIT();
    };

    // ---------- GEMM phase: 3-split HMMA; k-halves merged into scr (no gmem) ----------
    auto computePhase = [&](int offWhi, int offWlo, int offAhi, int offAlo, int st,
                            int ks0, int ks1) {
        float acc[2][4][4];
        #pragma unroll
        for (int f = 0; f < 2; f++)
            #pragma unroll
            for (int g = 0; g < 4; g++)
                #pragma unroll
                for (int i = 0; i < 4; i++) acc[f][g][i] = 0.f;

        const __nv_bfloat16* Ah = sm + offAhi;
        const __nv_bfloat16* Al = sm + offAlo;
        const __nv_bfloat16* Wh = sm + offWhi;
        const __nv_bfloat16* Wl = sm + offWlo;
        const int r00 = wm * 32 + q;

        for (int kst = ks0; kst < ks1; ++kst) {
            const int kb = kst * 16 + tg2;
            unsigned ah[2][4], al[2][4], bh[4][2], bl[4][2];
            #pragma unroll
            for (int f = 0; f < 2; f++) {
                int r = (r00 + f * 16) * st;
                ah[f][0] = *(const unsigned*)(Ah + r + kb);
                ah[f][1] = *(const unsigned*)(Ah + r + 8 * st + kb);
                ah[f][2] = *(const unsigned*)(Ah + r + kb + 8);
                ah[f][3] = *(const unsigned*)(Ah + r + 8 * st + kb + 8);
                al[f][0] = *(const unsigned*)(Al + r + kb);
                al[f][1] = *(const unsigned*)(Al + r + 8 * st + kb);
                al[f][2] = *(const unsigned*)(Al + r + kb + 8);
                al[f][3] = *(const unsigned*)(Al + r + 8 * st + kb + 8);
            }
            #pragma unroll
            for (int g = 0; g < 4; g++) {
                int nr = (wn * 32 + g * 8 + q) * st;
                bh[g][0] = *(const unsigned*)(Wh + nr + kb);
                bh[g][1] = *(const unsigned*)(Wh + nr + kb + 8);
                bl[g][0] = *(const unsigned*)(Wl + nr + kb);
                bl[g][1] = *(const unsigned*)(Wl + nr + kb + 8);
            }
            #pragma unroll
            for (int f = 0; f < 2; f++)
                #pragma unroll
                for (int g = 0; g < 4; g++) {
                    mma16816(acc[f][g], ah[f], bh[g]);
                    mma16816(acc[f][g], al[f], bh[g]);
                    mma16816(acc[f][g], ah[f], bl[g]);
                }
        }
        if (wk == 1) {
            #pragma unroll
            for (int f = 0; f < 2; f++)
                #pragma unroll
                for (int g = 0; g < 4; g++) {
                    int r = wm * 32 + f * 16 + q;
                    int c = wn * 32 + g * 8 + tg2;
                    *(float2*)(scr + r * SCR_STRIDE + c) =
                        make_float2(acc[f][g][0], acc[f][g][1]);
                    *(float2*)(scr + (r + 8) * SCR_STRIDE + c) =
                        make_float2(acc[f][g][2], acc[f][g][3]);
                }
        }
        __syncthreads();
        if (wk == 0) {
            #pragma unroll
            for (int f = 0; f < 2; f++)
                #pragma unroll
                for (int g = 0; g < 4; g++) {
                    int r = wm * 32 + f * 16 + q;
                    int c = wn * 32 + g * 8 + tg2;
                    float2 o0 = *(const float2*)(scr + r * SCR_STRIDE + c);
                    float2 o1 = *(const float2*)(scr + (r + 8) * SCR_STRIDE + c);
                    *(float2*)(scr + r * SCR_STRIDE + c) =
                        make_float2(acc[f][g][0] + o0.x, acc[f][g][1] + o0.y);
                    *(float2*)(scr + (r + 8) * SCR_STRIDE + c) =
                        make_float2(acc[f][g][2] + o1.x, acc[f][g][3] + o1.y);
                }
        }
    };

    // ---------- cluster reduce: sum 4 CTAs' scr via DSMEM + tanh + split-store ----------
    auto reduceC = [&](const float4& bias,
                       __nv_bfloat16* __restrict__ dhi, __nv_bfloat16* __restrict__ dlo) {
        float4 p0 = ld_dsmem_f4(mapa_rank(scr_off, 0));
        float4 p1 = ld_dsmem_f4(mapa_rank(scr_off, 1));
        float4 p2 = ld_dsmem_f4(mapa_rank(scr_off, 2));
        float4 p3 = ld_dsmem_f4(mapa_rank(scr_off, 3));
        float4 s;
        s.x = bias.x + p0.x + p1.x + p2.x + p3.x;
        s.y = bias.y + p0.y + p1.y + p2.y + p3.y;
        s.z = bias.z + p0.z + p1.z + p2.z + p3.z;
        s.w = bias.w + p0.w + p1.w + p2.w + p3.w;
        float h0 = tanhf(s.x), h1 = tanhf(s.y), h2 = tanhf(s.z), h3 = tanhf(s.w);
        __nv_bfloat16 hi0,hi1,hi2,hi3, lo0,lo1,lo2,lo3;
        split_bf16(h0,hi0,lo0); split_bf16(h1,hi1,lo1);
        split_bf16(h2,hi2,lo2); split_bf16(h3,hi3,lo3);
        __nv_bfloat162 ph0 = __halves2bfloat162(hi0,hi1), ph1 = __halves2bfloat162(hi2,hi3);
        __nv_bfloat162 pl0 = __halves2bfloat162(lo0,lo1), pl1 = __halves2bfloat162(lo2,lo3);
        uint2 uh, ul;
        uh.x = *(unsigned*)&ph0; uh.y = *(unsigned*)&ph1;
        ul.x = *(unsigned*)&pl0; ul.y = *(unsigned*)&pl1;
        size_t doff = (size_t)(m0 + rr) * HID + n0 + cc;
        __stcg((uint2*)(dhi + doff), uh);
        __stcg((uint2*)(dlo + doff), ul);
    };

    const int ksA0 = wk ? 5 : 0, ksA1 = wk ? 9 : 5;
    const int ksB0 = wk ? 8 : 0, ksB1 = wk ? 16 : 8;

    // ============================ main pipelined loop ============================
    // step t: A(t) [reads h1(t-1)], B(t-1) [reads h1(t-1), h2(t-2)];
    // publishes h1(t), h2(t-1). ONE grid barrier per step.
    for (int t = 0; t < SEQ; ++t) {
        const int pp = (t + 1) & 1, pc = t & 1;
        const __nv_bfloat16* h1phi = g_H1hi[pp]; const __nv_bfloat16* h1plo = g_H1lo[pp];
        const __nv_bfloat16* h2phi = g_H2hi[pc]; const __nv_bfloat16* h2plo = g_H2lo[pc];

        stageA_async(t, h1phi, h1plo);
        if (t > 0) {
            stageB_async(h1phi, h1plo, h2phi, h2plo);
            CP_WAIT(1);
        } else {
            CP_WAIT(0);
        }
        __syncthreads();
        computePhase(OFF_WA_HI, OFF_WA_LO, OFF_AA_HI, OFF_AA_LO, SA, ksA0, ksA1);
        CLUSTER_SYNC();                     // scr(A) visible cluster-wide
        reduceC(biasA, g_H1hi[pc], g_H1lo[pc]);
        if (t > 0) {
            CP_WAIT(0);                     // B staging landed (per-thread)
            CLUSTER_SYNC();                 // peers done reading scr(A); B smem visible CTA-wide
            computePhase(OFF_WB_HI, OFF_WB_LO, OFF_AB_HI, OFF_AB_LO, SB, ksB0, ksB1);
            CLUSTER_SYNC();                 // scr(B) visible cluster-wide
            reduceC(biasB, g_H2hi[pp], g_H2lo[pp]);
        }
        grid_sync(leaf);                    // publish h1(t), h2(t-1)
    }
    // epilogue: B(511): h1(511) in buf1, h2(510) in buf0 -> h2(511) in buf1
    stageB_async(g_H1hi[1], g_H1lo[1], g_H2hi[0], g_H2lo[0]);
    CP_WAIT(0);
    CLUSTER_SYNC();
    computePhase(OFF_WB_HI, OFF_WB_LO, OFF_AB_HI, OFF_AB_LO, SB, ksB0, ksB1);
    CLUSTER_SYNC();
    reduceC(biasB, g_H2hi[1], g_H2lo[1]);
    grid_sync(leaf);

    // ============================ final FC ============================
    static __shared__ float red[8];
    for (int r = 0; r < 2; ++r) {
        int b = bid * 2 + r;
        float s = 0.f;
        for (int h = tid * 2; h < HID; h += NTH * 2) {
            unsigned uh = __ldcg((const unsigned*)(&g_H2hi[1][(size_t)b * HID + h]));
            unsigned ul = __ldcg((const unsigned*)(&g_H2lo[1][(size_t)b * HID + h]));
            __nv_bfloat162 vh = *(__nv_bfloat162*)&uh;
            __nv_bfloat162 vl = *(__nv_bfloat162*)&ul;
            float v0 = __bfloat162float(__low2bfloat16(vh)) + __bfloat162float(__low2bfloat16(vl));
            float v1 = __bfloat162float(__high2bfloat16(vh)) + __bfloat162float(__high2bfloat16(vl));
            s += v0 * W_fc[h] + v1 * W_fc[h + 1];
        }
        #pragma unroll
        for (int off = 16; off; off >>= 1)
            s += __shfl_down_sync(0xffffffffu, s, off);
        if ((tid & 31) == 0) red[tid >> 5] = s;
        __syncthreads();
        if (tid == 0) {
            float tot = b_fc[0];
            #pragma unroll
            for (int w = 0; w < 8; w++) tot += red[w];
            out[b] = tot;
        }
        __syncthreads();
    }
}

extern "C" void kernel_launch(void* const* d_in, const int* in_sizes, int n_in,
                              void* d_out, int out_size) {
    (void)in_sizes; (void)n_in; (void)out_size;
    const float* x     = (const float*)d_in[0];
    const float* W_ih0 = (const float*)d_in[1];
    const float* W_hh0 = (const float*)d_in[2];
    const float* b_ih0 = (const float*)d_in[3];
    const float* b_hh0 = (const float*)d_in[4];
    const float* W_ih1 = (const float*)d_in[5];
    const float* W_hh1 = (const float*)d_in[6];
    const float* b_ih1 = (const float*)d_in[7];
    const float* b_hh1 = (const float*)d_in[8];
    const float* W_fc  = (const float*)d_in[9];
    const float* b_fc  = (const float*)d_in[10];
    float* out = (float*)d_out;

    cudaFuncSetAttribute(rnn_hmma,
                         cudaFuncAttributeMaxDynamicSharedMemorySize, SMEM_BYTES);
    rnn_hmma<<<GRIDN, NTH, SMEM_BYTES>>>(
        x, W_ih0, W_hh0, b_ih0, b_hh0,
        W_ih1, W_hh1, b_ih1, b_hh1, W_fc, b_fc, out);
}

// round 9
// speedup vs baseline: 3.4934x; 1.1730x over previous
#include <cuda_runtime.h>
#include <cuda_bf16.h>
#include <cstddef>

#define BATCH 256
#define SEQ   512
#define DIN   64
#define HID   512
#define GRIDN 128
#define NTH   256

#define TM 64
#define TN 64
#define KA_PER 144          // 576 / 4
#define KB_PER 256          // 1024 / 4

#define SA 152              // A-phase row stride (bf16 elems)
#define SB 264              // B-phase row stride

#define OFF_WA_HI 0
#define OFF_WA_LO (OFF_WA_HI + 64 * SA)
#define OFF_AA_HI (OFF_WA_LO + 64 * SA)
#define OFF_AA_LO (OFF_AA_HI + 64 * SA)
#define OFF_WB_HI (OFF_AA_LO + 64 * SA)
#define OFF_WB_LO (OFF_WB_HI + 64 * SB)
#define OFF_AB_HI (OFF_WB_LO + 64 * SB)
#define OFF_AB_LO (OFF_AB_HI + 64 * SB)
#define ELEMS_TOT (OFF_AB_LO + 64 * SB)          // 106,496 bf16 = 212,992 B
#define SCR_STRIDE 68                            // fp32; rows 16B-aligned
#define SMEM_BYTES (ELEMS_TOT * 2 + 64 * SCR_STRIDE * 4)   // 230,400 B

typedef unsigned long long ull;

// ---------------- cross-CTA state (static scratch; allocation-free) ----------------
__device__ __nv_bfloat16 g_Xhi[BATCH * SEQ * DIN];
__device__ __nv_bfloat16 g_Xlo[BATCH * SEQ * DIN];
__device__ __nv_bfloat16 g_H1hi[2][BATCH * HID], g_H1lo[2][BATCH * HID];
__device__ __nv_bfloat16 g_H2hi[2][BATCH * HID], g_H2lo[2][BATCH * HID];

struct __align__(128) Line { unsigned v; unsigned pad[31]; };
__device__ Line g_leaf[8];
__device__ Line g_root;
__device__ Line g_gen;
__device__ Line g_gcnt[4];     // per-row-group barrier counters
__device__ Line g_ggen[4];     // per-row-group generations

// full-grid tree barrier (init only)
__device__ __forceinline__ void grid_sync_init(int leaf) {
    __syncthreads();
    if (threadIdx.x == 0) {
        unsigned gen = *(volatile unsigned*)&g_gen.v;
        __threadfence();
        if (atomicAdd(&g_leaf[leaf].v, 1u) == 15u) {
            g_leaf[leaf].v = 0u;
            __threadfence();
            if (atomicAdd(&g_root.v, 1u) == 7u) {
                g_root.v = 0u;
                __threadfence();
                *(volatile unsigned*)&g_gen.v = gen + 1u;
            } else {
                while (*(volatile unsigned*)&g_gen.v == gen) __nanosleep(16);
            }
        } else {
            while (*(volatile unsigned*)&g_gen.v == gen) __nanosleep(16);
        }
        __threadfence();
    }
    __syncthreads();
}

// per-row-group 32-CTA barrier
__device__ __forceinline__ void group_bar(int grp) {
    __syncthreads();
    if (threadIdx.x == 0) {
        unsigned gen = *(volatile unsigned*)&g_ggen[grp].v;
        __threadfence();
        if (atomicAdd(&g_gcnt[grp].v, 1u) == 31u) {
            g_gcnt[grp].v = 0u;
            __threadfence();
            *(volatile unsigned*)&g_ggen[grp].v = gen + 1u;
        } else {
            while (*(volatile unsigned*)&g_ggen[grp].v == gen) __nanosleep(16);
        }
        __threadfence();
    }
    __syncthreads();
}

#define CLUSTER_SYNC() do { \
    asm volatile("barrier.cluster.arrive.aligned;" ::: "memory"); \
    asm volatile("barrier.cluster.wait.aligned;" ::: "memory"); \
} while (0)

__device__ __forceinline__ unsigned mapa_rank(unsigned smaddr, unsigned rank) {
    unsigned r;
    asm("mapa.shared::cluster.u32 %0, %1, %2;" : "=r"(r) : "r"(smaddr), "r"(rank));
    return r;
}
__device__ __forceinline__ float4 ld_dsmem_f4(unsigned addr) {
    float4 v;
    asm volatile("ld.shared::cluster.v4.f32 {%0,%1,%2,%3}, [%4];"
                 : "=f"(v.x), "=f"(v.y), "=f"(v.z), "=f"(v.w) : "r"(addr));
    return v;
}

__device__ __forceinline__ void mma16816(float* c, const unsigned* a, const unsigned* b) {
    asm volatile(
        "mma.sync.aligned.m16n8k16.row.col.f32.bf16.bf16.f32 "
        "{%0,%1,%2,%3}, {%4,%5,%6,%7}, {%8,%9}, {%0,%1,%2,%3};"
        : "+f"(c[0]), "+f"(c[1]), "+f"(c[2]), "+f"(c[3])
        : "r"(a[0]), "r"(a[1]), "r"(a[2]), "r"(a[3]), "r"(b[0]), "r"(b[1]));
}

#define CP16(dst_u32, src_ptr) \
    asm volatile("cp.async.cg.shared.global [%0], [%1], 16;" \
                 :: "r"(dst_u32), "l"(src_ptr))
#define CP_COMMIT() asm volatile("cp.async.commit_group;")
#define CP_WAIT(n)  asm volatile("cp.async.wait_group %0;" :: "n"(n))

__device__ __forceinline__ void split_bf16(float v, __nv_bfloat16& hi, __nv_bfloat16& lo) {
    hi = __float2bfloat16_rn(v);
    lo = __float2bfloat16_rn(v - __bfloat162float(hi));
}

__global__ void __launch_bounds__(NTH, 1) __cluster_dims__(4, 1, 1) rnn_hmma(
    const float* __restrict__ x,
    const float* __restrict__ W_ih0, const float* __restrict__ W_hh0,
    const float* __restrict__ b_ih0, const float* __restrict__ b_hh0,
    const float* __restrict__ W_ih1, const float* __restrict__ W_hh1,
    const float* __restrict__ b_ih1, const float* __restrict__ b_hh1,
    const float* __restrict__ W_fc,  const float* __restrict__ b_fc,
    float* __restrict__ out)
{
    const int tid  = threadIdx.x;
    const int bid  = blockIdx.x;
    const int leaf = bid & 7;
    const int grp  = bid >> 5;       // row group (mt)
    const int ks   = bid & 3;        // cluster rank
    const int tile = bid >> 2;
    const int mt   = tile >> 3;
    const int nt   = tile & 7;
    const int m0   = mt * TM;
    const int n0   = nt * TN;

    extern __shared__ __nv_bfloat16 sm[];
    float* scrA = (float*)(sm + ELEMS_TOT);
    float* scrB = (float*)(sm + OFF_AA_HI);      // aliases AA staging (dead in phase B)
    const unsigned sm_u32   = (unsigned)__cvta_generic_to_shared(sm);
    const unsigned scrA_u32 = sm_u32 + ELEMS_TOT * 2;
    const unsigned scrB_u32 = sm_u32 + OFF_AA_HI * 2;

    // ---------- one-time: split weight slices -> SMEM ----------
    {
        const int kb = ks * KA_PER;
        for (int idx = tid; idx < 64 * KA_PER; idx += NTH) {
            int n = idx / KA_PER, k = idx - n * KA_PER;
            int kg = kb + k;
            float v = (kg < DIN) ? W_ih0[(n0 + n) * DIN + kg]
                                 : W_hh0[(n0 + n) * HID + (kg - DIN)];
            __nv_bfloat16 hi, lo; split_bf16(v, hi, lo);
            sm[OFF_WA_HI + n * SA + k] = hi;
            sm[OFF_WA_LO + n * SA + k] = lo;
        }
        const int kbb = ks * KB_PER;
        for (int idx = tid; idx < 64 * KB_PER; idx += NTH) {
            int n = idx / KB_PER, k = idx - n * KB_PER;
            int kg = kbb + k;
            float v = (kg < HID) ? W_ih1[(n0 + n) * HID + kg]
                                 : W_hh1[(n0 + n) * HID + (kg - HID)];
            __nv_bfloat16 hi, lo; split_bf16(v, hi, lo);
            sm[OFF_WB_HI + n * SB + k] = hi;
            sm[OFF_WB_LO + n * SB + k] = lo;
        }
    }
    // ---------- one-time: pre-split x ----------
    {
        const int total = BATCH * SEQ * DIN;
        for (int i = (bid * NTH + tid) * 4; i < total; i += GRIDN * NTH * 4) {
            float4 v = *(const float4*)(x + i);
            __nv_bfloat16 h0,h1,h2,h3,l0,l1,l2,l3;
            split_bf16(v.x,h0,l0); split_bf16(v.y,h1,l1);
            split_bf16(v.z,h2,l2); split_bf16(v.w,h3,l3);
            *(__nv_bfloat162*)(g_Xhi + i)     = __halves2bfloat162(h0, h1);
            *(__nv_bfloat162*)(g_Xhi + i + 2) = __halves2bfloat162(h2, h3);
            *(__nv_bfloat162*)(g_Xlo + i)     = __halves2bfloat162(l0, l1);
            *(__nv_bfloat162*)(g_Xlo + i + 2) = __halves2bfloat162(l2, l3);
        }
    }
    // ---------- zero t=-1 states (buffer 1) ----------
    {
        const int per = (BATCH * HID) / GRIDN;
        const int base = bid * per;
        __nv_bfloat162 z = __halves2bfloat162(__float2bfloat16(0.f), __float2bfloat16(0.f));
        for (int i = tid * 2; i < per; i += NTH * 2) {
            *(__nv_bfloat162*)(&g_H1hi[1][base + i]) = z;
            *(__nv_bfloat162*)(&g_H1lo[1][base + i]) = z;
            *(__nv_bfloat162*)(&g_H2hi[1][base + i]) = z;
            *(__nv_bfloat162*)(&g_H2lo[1][base + i]) = z;
        }
    }
    grid_sync_init(leaf);

    // ---------- roles ----------
    const int lane = tid & 31;
    const int wid  = tid >> 5;
    const int wm   = wid & 1;
    const int wn   = (wid >> 1) & 1;
    const int wk   = wid >> 2;
    const int q    = lane >> 2;
    const int tg2  = (lane & 3) * 2;

    const int s_k   = lane * 8;
    const int s_row = wid;

    // reduce role: cluster-wide 1024 threads cover 64x64 tile
    const int gtid = ks * NTH + tid;
    const int rr = gtid >> 4;
    const int cc = (gtid & 15) << 2;
    float4 biasA, biasB;
    {
        float4 bi = *(const float4*)(b_ih0 + n0 + cc);
        float4 bh = *(const float4*)(b_hh0 + n0 + cc);
        biasA = make_float4(bi.x+bh.x, bi.y+bh.y, bi.z+bh.z, bi.w+bh.w);
        bi = *(const float4*)(b_ih1 + n0 + cc);
        bh = *(const float4*)(b_hh1 + n0 + cc);
        biasB = make_float4(bi.x+bh.x, bi.y+bh.y, bi.z+bh.z, bi.w+bh.w);
    }
    const unsigned redoff = (unsigned)(rr * SCR_STRIDE + cc) * 4u;

    // ---------- async staging ----------
    auto stageA_async = [&](int t, const __nv_bfloat16* h1phi, const __nv_bfloat16* h1plo) {
        if (s_k < KA_PER) {
            const int kg = ks * KA_PER + s_k;
            #pragma unroll
            for (int it = 0; it < 8; ++it) {
                int row = s_row + it * 8;
                int mgr = m0 + row;
                const __nv_bfloat16 *ph, *pl;
                if (kg < DIN) {
                    size_t off = (size_t)mgr * (SEQ * DIN) + (size_t)t * DIN + kg;
                    ph = g_Xhi + off; pl = g_Xlo + off;
                } else {
                    size_t off = (size_t)mgr * HID + (kg - DIN);
                    ph = h1phi + off; pl = h1plo + off;
                }
                CP16(sm_u32 + (OFF_AA_HI + row * SA + s_k) * 2, ph);
                CP16(sm_u32 + (OFF_AA_LO + row * SA + s_k) * 2, pl);
            }
        }
        CP_COMMIT();
    };
    auto stageB_async = [&](const __nv_bfloat16* h1phi, const __nv_bfloat16* h1plo,
                            const __nv_bfloat16* h2phi, const __nv_bfloat16* h2plo) {
        const int kg = ks * KB_PER + s_k;
        const int koff = (ks < 2) ? kg : kg - HID;
        const __nv_bfloat16* shi = (ks < 2) ? h1phi : h2phi;
        const __nv_bfloat16* slo = (ks < 2) ? h1plo : h2plo;
        #pragma unroll
        for (int it = 0; it < 8; ++it) {
            int row = s_row + it * 8;
            size_t off = (size_t)(m0 + row) * HID + koff;
            CP16(sm_u32 + (OFF_AB_HI + row * SB + s_k) * 2, shi + off);
            CP16(sm_u32 + (OFF_AB_LO + row * SB + s_k) * 2, slo + off);
        }
        CP_COMMIT();
    };

    // ---------- GEMM phase: 3-split HMMA; k-halves merged into scrp ----------
    auto computePhase = [&](int offWhi, int offWlo, int offAhi, int offAlo, int st,
                            int ks0, int ks1, float* __restrict__ scrp) {
        float acc[2][4][4];
        #pragma unroll
        for (int f = 0; f < 2; f++)
            #pragma unroll
            for (int g = 0; g < 4; g++)
                #pragma unroll
                for (int i = 0; i < 4; i++) acc[f][g][i] = 0.f;

        const __nv_bfloat16* Ah = sm + offAhi;
        const __nv_bfloat16* Al = sm + offAlo;
        const __nv_bfloat16* Wh = sm + offWhi;
        const __nv_bfloat16* Wl = sm + offWlo;
        const int r00 = wm * 32 + q;

        for (int kst = ks0; kst < ks1; ++kst) {
            const int kb = kst * 16 + tg2;
            unsigned ah[2][4], al[2][4], bh[4][2], bl[4][2];
            #pragma unroll
            for (int f = 0; f < 2; f++) {
                int r = (r00 + f * 16) * st;
                ah[f][0] = *(const unsigned*)(Ah + r + kb);
                ah[f][1] = *(const unsigned*)(Ah + r + 8 * st + kb);
                ah[f][2] = *(const unsigned*)(Ah + r + kb + 8);
                ah[f][3] = *(const unsigned*)(Ah + r + 8 * st + kb + 8);
                al[f][0] = *(const unsigned*)(Al + r + kb);
                al[f][1] = *(const unsigned*)(Al + r + 8 * st + kb);
                al[f][2] = *(const unsigned*)(Al + r + kb + 8);
                al[f][3] = *(const unsigned*)(Al + r + 8 * st + kb + 8);
            }
            #pragma unroll
            for (int g = 0; g < 4; g++) {
                int nr = (wn * 32 + g * 8 + q) * st;
                bh[g][0] = *(const unsigned*)(Wh + nr + kb);
                bh[g][1] = *(const unsigned*)(Wh + nr + kb + 8);
                bl[g][0] = *(const unsigned*)(Wl + nr + kb);
                bl[g][1] = *(const unsigned*)(Wl + nr + kb + 8);
            }
            #pragma unroll
            for (int f = 0; f < 2; f++)
                #pragma unroll
                for (int g = 0; g < 4; g++) {
                    mma16816(acc[f][g], ah[f], bh[g]);
                    mma16816(acc[f][g], al[f], bh[g]);
                    mma16816(acc[f][g], ah[f], bl[g]);
                }
        }
        if (wk == 1) {
            #pragma unroll
            for (int f = 0; f < 2; f++)
                #pragma unroll
                for (int g = 0; g < 4; g++) {
                    int r = wm * 32 + f * 16 + q;
                    int c = wn * 32 + g * 8 + tg2;
                    *(float2*)(scrp + r * SCR_STRIDE + c) =
                        make_float2(acc[f][g][0], acc[f][g][1]);
                    *(float2*)(scrp + (r + 8) * SCR_STRIDE + c) =
                        make_float2(acc[f][g][2], acc[f][g][3]);
                }
        }
        __syncthreads();
        if (wk == 0) {
            #pragma unroll
            for (int f = 0; f < 2; f++)
                #pragma unroll
                for (int g = 0; g < 4; g++) {
                    int r = wm * 32 + f * 16 + q;
                    int c = wn * 32 + g * 8 + tg2;
                    float2 o0 = *(const float2*)(scrp + r * SCR_STRIDE + c);
                    float2 o1 = *(const float2*)(scrp + (r + 8) * SCR_STRIDE + c);
                    *(float2*)(scrp + r * SCR_STRIDE + c) =
                        make_float2(acc[f][g][0] + o0.x, acc[f][g][1] + o0.y);
                    *(float2*)(scrp + (r + 8) * SCR_STRIDE + c) =
                        make_float2(acc[f][g][2] + o1.x, acc[f][g][3] + o1.y);
                }
        }
    };

    // ---------- cluster reduce via DSMEM + tanh + split-store ----------
    auto reduceC = [&](unsigned scr_base, const float4& bias,
                       __nv_bfloat16* __restrict__ dhi, __nv_bfloat16* __restrict__ dlo) {
        const unsigned a = scr_base + redoff;
        float4 p0 = ld_dsmem_f4(mapa_rank(a, 0));
        float4 p1 = ld_dsmem_f4(mapa_rank(a, 1));
        float4 p2 = ld_dsmem_f4(mapa_rank(a, 2));
        float4 p3 = ld_dsmem_f4(mapa_rank(a, 3));
        float4 s;
        s.x = bias.x + p0.x + p1.x + p2.x + p3.x;
        s.y = bias.y + p0.y + p1.y + p2.y + p3.y;
        s.z = bias.z + p0.z + p1.z + p2.z + p3.z;
        s.w = bias.w + p0.w + p1.w + p2.w + p3.w;
        float h0 = tanhf(s.x), h1 = tanhf(s.y), h2 = tanhf(s.z), h3 = tanhf(s.w);
        __nv_bfloat16 hi0,hi1,hi2,hi3, lo0,lo1,lo2,lo3;
        split_bf16(h0,hi0,lo0); split_bf16(h1,hi1,lo1);
        split_bf16(h2,hi2,lo2); split_bf16(h3,hi3,lo3);
        __nv_bfloat162 ph0 = __halves2bfloat162(hi0,hi1), ph1 = __halves2bfloat162(hi2,hi3);
        __nv_bfloat162 pl0 = __halves2bfloat162(lo0,lo1), pl1 = __halves2bfloat162(lo2,lo3);
        uint2 uh, ul;
        uh.x = *(unsigned*)&ph0; uh.y = *(unsigned*)&ph1;
        ul.x = *(unsigned*)&pl0; ul.y = *(unsigned*)&pl1;
        size_t doff = (size_t)(m0 + rr) * HID + n0 + cc;
        __stcg((uint2*)(dhi + doff), uh);
        __stcg((uint2*)(dlo + doff), ul);
    };

    const int ksA0 = wk ? 5 : 0, ksA1 = wk ? 9 : 5;
    const int ksB0 = wk ? 8 : 0, ksB1 = wk ? 16 : 8;

    // ============================ main pipelined loop ============================
    // step t: A(t) [reads h1(t-1)], B(t-1) [reads h1(t-1), h2(t-2)];
    // publishes h1(t), h2(t-1). ONE 32-CTA row-group barrier per step.
    for (int t = 0; t < SEQ; ++t) {
        const int pp = (t + 1) & 1, pc = t & 1;
        const __nv_bfloat16* h1phi = g_H1hi[pp]; const __nv_bfloat16* h1plo = g_H1lo[pp];
        const __nv_bfloat16* h2phi = g_H2hi[pc]; const __nv_bfloat16* h2plo = g_H2lo[pc];

        stageA_async(t, h1phi, h1plo);
        if (t > 0) {
            stageB_async(h1phi, h1plo, h2phi, h2plo);
            CP_WAIT(1);
        } else {
            CP_WAIT(0);
        }
        __syncthreads();
        computePhase(OFF_WA_HI, OFF_WA_LO, OFF_AA_HI, OFF_AA_LO, SA, ksA0, ksA1, scrA);
        CLUSTER_SYNC();                     // scrA visible cluster-wide; AA reads done CTA-wide
        reduceC(scrA_u32, biasA, g_H1hi[pc], g_H1lo[pc]);
        if (t > 0) {
            CP_WAIT(0);                     // AB staging landed (per-thread)
            __syncthreads();                // AB visible CTA-wide
            computePhase(OFF_WB_HI, OFF_WB_LO, OFF_AB_HI, OFF_AB_LO, SB, ksB0, ksB1, scrB);
            CLUSTER_SYNC();                 // scrB visible cluster-wide
            reduceC(scrB_u32, biasB, g_H2hi[pp], g_H2lo[pp]);
        }
        group_bar(grp);                     // publish h1(t), h2(t-1) within row group
    }
    // epilogue: B(511): h1(511) in buf1, h2(510) in buf0 -> h2(511) in buf1
    stageB_async(g_H1hi[1], g_H1lo[1], g_H2hi[0], g_H2lo[0]);
    CP_WAIT(0);
    __syncthreads();
    computePhase(OFF_WB_HI, OFF_WB_LO, OFF_AB_HI, OFF_AB_LO, SB, ksB0, ksB1, scrB);
    CLUSTER_SYNC();
    reduceC(scrB_u32, biasB, g_H2hi[1], g_H2lo[1]);
    group_bar(grp);

    // ============================ final FC (needs only own row group's h2) ============================
    static __shared__ float red[8];
    for (int r = 0; r < 2; ++r) {
        int b = bid * 2 + r;
        float s = 0.f;
        for (int h = tid * 2; h < HID; h += NTH * 2) {
            unsigned uh = __ldcg((const unsigned*)(&g_H2hi[1][(size_t)b * HID + h]));
            unsigned ul = __ldcg((const unsigned*)(&g_H2lo[1][(size_t)b * HID + h]));
            __nv_bfloat162 vh = *(__nv_bfloat162*)&uh;
            __nv_bfloat162 vl = *(__nv_bfloat162*)&ul;
            float v0 = __bfloat162float(__low2bfloat16(vh)) + __bfloat162float(__low2bfloat16(vl));
            float v1 = __bfloat162float(__high2bfloat16(vh)) + __bfloat162float(__high2bfloat16(vl));
            s += v0 * W_fc[h] + v1 * W_fc[h + 1];
        }
        #pragma unroll
        for (int off = 16; off; off >>= 1)
            s += __shfl_down_sync(0xffffffffu, s, off);
        if ((tid & 31) == 0) red[tid >> 5] = s;
        __syncthreads();
        if (tid == 0) {
            float tot = b_fc[0];
            #pragma unroll
            for (int w = 0; w < 8; w++) tot += red[w];
            out[b] = tot;
        }
        __syncthreads();
    }
}

extern "C" void kernel_launch(void* const* d_in, const int* in_sizes, int n_in,
                              void* d_out, int out_size) {
    (void)in_sizes; (void)n_in; (void)out_size;
    const float* x     = (const float*)d_in[0];
    const float* W_ih0 = (const float*)d_in[1];
    const float* W_hh0 = (const float*)d_in[2];
    const float* b_ih0 = (const float*)d_in[3];
    const float* b_hh0 = (const float*)d_in[4];
    const float* W_ih1 = (const float*)d_in[5];
    const float* W_hh1 = (const float*)d_in[6];
    const float* b_ih1 = (const float*)d_in[7];
    const float* b_hh1 = (const float*)d_in[8];
    const float* W_fc  = (const float*)d_in[9];
    const float* b_fc  = (const float*)d_in[10];
    float* out = (float*)d_out;

    cudaFuncSetAttribute(rnn_hmma,
                         cudaFuncAttributeMaxDynamicSharedMemorySize, SMEM_BYTES);
    rnn_hmma<<<GRIDN, NTH, SMEM_BYTES>>>(
        x, W_ih0, W_hh0, b_ih0, b_hh0,
        W_ih1, W_hh1, b_ih1, b_hh1, W_fc, b_fc, out);
}